// round 1
// baseline (speedup 1.0000x reference)
#include <cuda_runtime.h>

#define Bq 4
#define Tq 2048
#define Cq 1024
#define Hq 16
#define Dh 64

// Scratch (device globals — no allocation allowed in kernel_launch)
#define QKV_ELEMS (Bq*Hq*Tq*Dh)   // 8,388,608 floats = 32 MB each
__device__ float g_Q[QKV_ELEMS];
__device__ float g_K[QKV_ELEMS];
__device__ float g_V[QKV_ELEMS];
__device__ float g_O[QKV_ELEMS];

// ---------------------------------------------------------------------------
// SGEMM: C[M,N] = A[M,K] @ B[N,K]^T   (128x128x16 block, 8x8 microtile)
// MODE 0: plain A, plain C
// MODE 1: plain A (=x), epilogue scatters into g_Q/g_K/g_V ([b,h,t,d] layout)
// MODE 2: A gathered from g_O ([b,h,t,d] -> [m=b*T+t, k=h*64+d]), plain C
// ---------------------------------------------------------------------------
#define BM 128
#define BN 128
#define BK 16

template<int MODE>
__global__ __launch_bounds__(256)
void sgemm_kernel(const float* __restrict__ A, const float* __restrict__ Bw,
                  float* __restrict__ C, int N, int K)
{
    __shared__ __align__(16) float As[BK * BM];
    __shared__ __align__(16) float Bs[BK * BN];

    const int tid = threadIdx.x;
    const int tx = tid & 15;        // 0..15
    const int ty = tid >> 4;        // 0..15
    const int bm = blockIdx.y * BM;
    const int bn = blockIdx.x * BN;

    float acc[8][8];
    #pragma unroll
    for (int i = 0; i < 8; i++)
        #pragma unroll
        for (int j = 0; j < 8; j++)
            acc[i][j] = 0.0f;

    for (int k0 = 0; k0 < K; k0 += BK) {
        #pragma unroll
        for (int v = 0; v < 2; v++) {
            int lin = tid + v * 256;          // 0..511 (float4 ids over 128x16 tile)
            int row = lin >> 2;               // 0..127
            int c4  = (lin & 3) << 2;         // 0,4,8,12

            float4 av;
            if (MODE == 2) {
                int m = bm + row;
                int k = k0 + c4;
                int b = m >> 11;              // /2048
                int t = m & 2047;
                int h = k >> 6;
                int d = k & 63;
                av = *(const float4*)(g_O + ((size_t)((b * Hq + h) * Tq + t)) * Dh + d);
            } else {
                av = *(const float4*)(A + (size_t)(bm + row) * K + k0 + c4);
            }
            As[(c4 + 0) * BM + row] = av.x;
            As[(c4 + 1) * BM + row] = av.y;
            As[(c4 + 2) * BM + row] = av.z;
            As[(c4 + 3) * BM + row] = av.w;

            float4 bv = *(const float4*)(Bw + (size_t)(bn + row) * K + k0 + c4);
            Bs[(c4 + 0) * BN + row] = bv.x;
            Bs[(c4 + 1) * BN + row] = bv.y;
            Bs[(c4 + 2) * BN + row] = bv.z;
            Bs[(c4 + 3) * BN + row] = bv.w;
        }
        __syncthreads();

        #pragma unroll
        for (int kk = 0; kk < BK; kk++) {
            float a[8], b[8];
            *(float4*)&a[0] = *(const float4*)&As[kk * BM + ty * 4];
            *(float4*)&a[4] = *(const float4*)&As[kk * BM + 64 + ty * 4];
            *(float4*)&b[0] = *(const float4*)&Bs[kk * BN + tx * 4];
            *(float4*)&b[4] = *(const float4*)&Bs[kk * BN + 64 + tx * 4];
            #pragma unroll
            for (int i = 0; i < 8; i++)
                #pragma unroll
                for (int j = 0; j < 8; j++)
                    acc[i][j] = fmaf(a[i], b[j], acc[i][j]);
        }
        __syncthreads();
    }

    #pragma unroll
    for (int ii = 0; ii < 8; ii++) {
        int m = bm + ((ii < 4) ? (ty * 4 + ii) : (64 + ty * 4 + ii - 4));
        #pragma unroll
        for (int jj = 0; jj < 8; jj++) {
            int n = bn + ((jj < 4) ? (tx * 4 + jj) : (64 + tx * 4 + jj - 4));
            float val = acc[ii][jj];
            if (MODE == 1) {
                int b = m >> 11;
                int t = m & 2047;
                int part = n >> 10;           // 0=Q 1=K 2=V
                int hh = (n & 1023) >> 6;
                int d  = n & 63;
                float* dst = (part == 0) ? g_Q : (part == 1) ? g_K : g_V;
                dst[((size_t)((b * Hq + hh) * Tq + t)) * Dh + d] = val;
            } else {
                C[(size_t)m * N + n] = val;
            }
        }
    }
}

// ---------------------------------------------------------------------------
// RoPE applied in-place to g_Q and g_K.
// rot_half([u1,u2]) = [-u2, u1];  q' = q*cos + rot_half(q)*sin
// ---------------------------------------------------------------------------
__global__ void rope_kernel(const float* __restrict__ cosT, const float* __restrict__ sinT)
{
    int idx  = blockIdx.x * blockDim.x + threadIdx.x;   // [0, B*H*T*32)
    int lane = idx & 31;
    int row  = idx >> 5;                                // [0, B*H*T)
    int t    = row & (Tq - 1);
    size_t base = (size_t)row * Dh;

    float c0 = cosT[t * Dh + lane];
    float c1 = cosT[t * Dh + 32 + lane];
    float s0 = sinT[t * Dh + lane];
    float s1 = sinT[t * Dh + 32 + lane];

    float q0 = g_Q[base + lane], q1 = g_Q[base + 32 + lane];
    g_Q[base + lane]      = q0 * c0 - q1 * s0;
    g_Q[base + 32 + lane] = q1 * c1 + q0 * s1;

    float k0 = g_K[base + lane], k1 = g_K[base + 32 + lane];
    g_K[base + lane]      = k0 * c0 - k1 * s0;
    g_K[base + 32 + lane] = k1 * c1 + k0 * s1;
}

// ---------------------------------------------------------------------------
// Flash attention (causal). One block per (q-tile of 64 rows, bh).
// 256 threads: ty=tid/16 owns 4 q-rows, tx=tid%16 owns 4 cols.
// Q,K stored transposed [d][row] in smem (stride 68) so the S inner loop is
// 2x LDS.128 + 16 FFMA. K smem buffer is reused for P ([row][k], stride 64).
// ---------------------------------------------------------------------------
#define PADT 68
#define FLASH_SMEM ((2 * 64 * PADT + 64 * 64) * 4)   // 51200 bytes

__global__ __launch_bounds__(256)
void flash_kernel()
{
    extern __shared__ __align__(16) float sm[];
    float* Qs  = sm;                    // [64 d][PADT rows]
    float* KPs = sm + 64 * PADT;        // K as [64 d][PADT k]; then P as [64 row][64 k]
    float* Vs  = sm + 2 * 64 * PADT;    // [64 k][64 d]

    const int tid = threadIdx.x;
    const int tx = tid & 15;
    const int ty = tid >> 4;
    const int qt = blockIdx.x;          // 0..31
    const int bh = blockIdx.y;          // 0..63

    const float* Qg = g_Q + (size_t)bh * Tq * Dh + (size_t)qt * 64 * Dh;
    const float* Kg = g_K + (size_t)bh * Tq * Dh;
    const float* Vg = g_V + (size_t)bh * Tq * Dh;

    // Load Q tile transposed, pre-scaled by 1/sqrt(Dh)
    #pragma unroll
    for (int v = 0; v < 4; v++) {
        int lin = tid + v * 256;        // 0..1023 float4 ids
        int row = lin >> 4;
        int c4  = (lin & 15) << 2;
        float4 q = *(const float4*)(Qg + row * Dh + c4);
        Qs[(c4 + 0) * PADT + row] = q.x * 0.125f;
        Qs[(c4 + 1) * PADT + row] = q.y * 0.125f;
        Qs[(c4 + 2) * PADT + row] = q.z * 0.125f;
        Qs[(c4 + 3) * PADT + row] = q.w * 0.125f;
    }

    float m[4], l[4], o[4][4];
    #pragma unroll
    for (int i = 0; i < 4; i++) {
        m[i] = -1e30f;
        l[i] = 0.0f;
        #pragma unroll
        for (int j = 0; j < 4; j++) o[i][j] = 0.0f;
    }

    for (int kt = 0; kt <= qt; kt++) {
        __syncthreads();   // previous iteration's P/V reads complete
        const float* Kt = Kg + (size_t)kt * 64 * Dh;
        const float* Vt = Vg + (size_t)kt * 64 * Dh;
        #pragma unroll
        for (int v = 0; v < 4; v++) {
            int lin = tid + v * 256;
            int row = lin >> 4;
            int c4  = (lin & 15) << 2;
            float4 k4 = *(const float4*)(Kt + row * Dh + c4);
            KPs[(c4 + 0) * PADT + row] = k4.x;
            KPs[(c4 + 1) * PADT + row] = k4.y;
            KPs[(c4 + 2) * PADT + row] = k4.z;
            KPs[(c4 + 3) * PADT + row] = k4.w;
            float4 v4 = *(const float4*)(Vt + row * Dh + c4);
            *(float4*)(Vs + row * Dh + c4) = v4;
        }
        __syncthreads();

        // S = Q @ K^T  (4x4 microtile per thread)
        float s[4][4];
        #pragma unroll
        for (int i = 0; i < 4; i++)
            #pragma unroll
            for (int j = 0; j < 4; j++) s[i][j] = 0.0f;

        #pragma unroll 8
        for (int d = 0; d < 64; d++) {
            float a[4], b[4];
            *(float4*)a = *(const float4*)&Qs[d * PADT + ty * 4];
            *(float4*)b = *(const float4*)&KPs[d * PADT + tx * 4];
            #pragma unroll
            for (int i = 0; i < 4; i++)
                #pragma unroll
                for (int j = 0; j < 4; j++)
                    s[i][j] = fmaf(a[i], b[j], s[i][j]);
        }

        if (kt == qt) {
            #pragma unroll
            for (int i = 0; i < 4; i++)
                #pragma unroll
                for (int j = 0; j < 4; j++)
                    if (tx * 4 + j > ty * 4 + i) s[i][j] = -1e30f;
        }

        __syncthreads();   // all K reads done; KPs becomes P buffer

        #pragma unroll
        for (int i = 0; i < 4; i++) {
            float mx = fmaxf(fmaxf(s[i][0], s[i][1]), fmaxf(s[i][2], s[i][3]));
            mx = fmaxf(mx, __shfl_xor_sync(0xffffffffu, mx, 1));
            mx = fmaxf(mx, __shfl_xor_sync(0xffffffffu, mx, 2));
            mx = fmaxf(mx, __shfl_xor_sync(0xffffffffu, mx, 4));
            mx = fmaxf(mx, __shfl_xor_sync(0xffffffffu, mx, 8));
            float mn = fmaxf(m[i], mx);
            float alpha = __expf(m[i] - mn);
            m[i] = mn;
            float p0 = __expf(s[i][0] - mn);
            float p1 = __expf(s[i][1] - mn);
            float p2 = __expf(s[i][2] - mn);
            float p3 = __expf(s[i][3] - mn);
            float rs = (p0 + p1) + (p2 + p3);
            rs += __shfl_xor_sync(0xffffffffu, rs, 1);
            rs += __shfl_xor_sync(0xffffffffu, rs, 2);
            rs += __shfl_xor_sync(0xffffffffu, rs, 4);
            rs += __shfl_xor_sync(0xffffffffu, rs, 8);
            l[i] = l[i] * alpha + rs;
            #pragma unroll
            for (int j = 0; j < 4; j++) o[i][j] *= alpha;
            *(float4*)&KPs[(ty * 4 + i) * 64 + tx * 4] = make_float4(p0, p1, p2, p3);
        }
        __syncthreads();   // P visible to all

        // O += P @ V
        #pragma unroll 8
        for (int k = 0; k < 64; k++) {
            float vv[4];
            *(float4*)vv = *(const float4*)&Vs[k * Dh + tx * 4];
            #pragma unroll
            for (int i = 0; i < 4; i++) {
                float p = KPs[(ty * 4 + i) * 64 + k];
                #pragma unroll
                for (int j = 0; j < 4; j++)
                    o[i][j] = fmaf(p, vv[j], o[i][j]);
            }
        }
    }

    float* Og = g_O + (size_t)bh * Tq * Dh + (size_t)qt * 64 * Dh;
    #pragma unroll
    for (int i = 0; i < 4; i++) {
        float inv = 1.0f / l[i];
        *(float4*)(Og + (ty * 4 + i) * Dh + tx * 4) =
            make_float4(o[i][0] * inv, o[i][1] * inv, o[i][2] * inv, o[i][3] * inv);
    }
}

// ---------------------------------------------------------------------------
extern "C" void kernel_launch(void* const* d_in, const int* in_sizes, int n_in,
                              void* d_out, int out_size)
{
    (void)in_sizes; (void)n_in; (void)out_size;
    const float* x     = (const float*)d_in[0];
    const float* cosT  = (const float*)d_in[1];
    const float* sinT  = (const float*)d_in[2];
    const float* w_qkv = (const float*)d_in[3];
    const float* w_out = (const float*)d_in[4];
    float* out = (float*)d_out;

    cudaFuncSetAttribute(flash_kernel, cudaFuncAttributeMaxDynamicSharedMemorySize, FLASH_SMEM);

    // 1) QKV projection (+ scatter into [b,h,t,d])
    {
        dim3 grid(3 * Cq / BN, (Bq * Tq) / BM);   // (24, 64)
        sgemm_kernel<1><<<grid, 256>>>(x, w_qkv, nullptr, 3 * Cq, Cq);
    }
    // 2) RoPE on Q,K
    {
        int total = Bq * Hq * Tq * 32;
        rope_kernel<<<total / 256, 256>>>(cosT, sinT);
    }
    // 3) Causal flash attention
    {
        dim3 grid(Tq / 64, Bq * Hq);              // (32, 64)
        flash_kernel<<<grid, 256, FLASH_SMEM>>>();
    }
    // 4) Output projection (gather from g_O)
    {
        dim3 grid(Cq / BN, (Bq * Tq) / BM);       // (8, 64)
        sgemm_kernel<2><<<grid, 256>>>(x, w_out, out, Cq, Cq);
    }
}

// round 3
// speedup vs baseline: 1.4293x; 1.4293x over previous
#include <cuda_runtime.h>
#include <cuda_bf16.h>
#include <cstdint>

#define Bq 4
#define Tq 2048
#define Cq 1024
#define Hq 16
#define Dh 64
#define MROWS (Bq*Tq)          // 8192

// ---------------------------------------------------------------------------
// Device-global scratch (no allocations allowed)
// ---------------------------------------------------------------------------
__device__ float g_Q[MROWS*Cq/16*16];    // [b,h,t,d]
__device__ float g_K[MROWS*Cq];          // [b,h,t,d]
__device__ float g_V[MROWS*Cq];          // [b,h,t,d]
__device__ float g_O[MROWS*Cq];          // [b,t,h,d] == [m,k] for out-proj

__device__ __nv_bfloat16 g_x_hi[MROWS*Cq],  g_x_lo[MROWS*Cq];
__device__ __nv_bfloat16 g_wq_hi[3*Cq*Cq],  g_wq_lo[3*Cq*Cq];
__device__ __nv_bfloat16 g_wo_hi[Cq*Cq],    g_wo_lo[Cq*Cq];
__device__ __nv_bfloat16 g_o_hi[MROWS*Cq],  g_o_lo[MROWS*Cq];

// ---------------------------------------------------------------------------
// helpers
// ---------------------------------------------------------------------------
__device__ __forceinline__ uint32_t s2u(const void* p){
    uint32_t a;
    asm("{ .reg .u64 t; cvta.to.shared.u64 t, %1; cvt.u32.u64 %0, t; }" : "=r"(a) : "l"(p));
    return a;
}
__device__ __forceinline__ void cp16(uint32_t dst, const void* src){
    asm volatile("cp.async.cg.shared.global [%0], [%1], 16;" :: "r"(dst), "l"(src));
}
__device__ __forceinline__ void ldmx4(uint32_t* r, uint32_t addr){
    asm volatile("ldmatrix.sync.aligned.m8n8.x4.shared.b16 {%0,%1,%2,%3}, [%4];"
                 : "=r"(r[0]), "=r"(r[1]), "=r"(r[2]), "=r"(r[3]) : "r"(addr));
}
__device__ __forceinline__ void mma16816(float* c, const uint32_t* a, const uint32_t* b){
    asm volatile(
        "mma.sync.aligned.m16n8k16.row.col.f32.bf16.bf16.f32 "
        "{%0,%1,%2,%3}, {%4,%5,%6,%7}, {%8,%9}, {%0,%1,%2,%3};"
        : "+f"(c[0]), "+f"(c[1]), "+f"(c[2]), "+f"(c[3])
        : "r"(a[0]), "r"(a[1]), "r"(a[2]), "r"(a[3]), "r"(b[0]), "r"(b[1]));
}

// ---------------------------------------------------------------------------
// fp32 -> (bf16 hi, bf16 lo) split
// ---------------------------------------------------------------------------
__global__ void split_kernel(const float* __restrict__ src,
                             __nv_bfloat16* __restrict__ hi,
                             __nv_bfloat16* __restrict__ lo, int n4)
{
    int i = blockIdx.x * blockDim.x + threadIdx.x;
    if (i >= n4) return;
    float4 v = ((const float4*)src)[i];
    __nv_bfloat16 h0 = __float2bfloat16(v.x);
    __nv_bfloat16 h1 = __float2bfloat16(v.y);
    __nv_bfloat16 h2 = __float2bfloat16(v.z);
    __nv_bfloat16 h3 = __float2bfloat16(v.w);
    __nv_bfloat16 l0 = __float2bfloat16(v.x - __bfloat162float(h0));
    __nv_bfloat16 l1 = __float2bfloat16(v.y - __bfloat162float(h1));
    __nv_bfloat16 l2 = __float2bfloat16(v.z - __bfloat162float(h2));
    __nv_bfloat16 l3 = __float2bfloat16(v.w - __bfloat162float(h3));
    ((__nv_bfloat162*)hi)[2*i]   = __halves2bfloat162(h0, h1);
    ((__nv_bfloat162*)hi)[2*i+1] = __halves2bfloat162(h2, h3);
    ((__nv_bfloat162*)lo)[2*i]   = __halves2bfloat162(l0, l1);
    ((__nv_bfloat162*)lo)[2*i+1] = __halves2bfloat162(l2, l3);
}

// ---------------------------------------------------------------------------
// HMMA (mma.sync bf16) GEMM, 3-pass compensated:
//   C = Ah@Bh^T + Ah@Bl^T + Al@Bh^T      A:[M,K], B:[N,K]
// Block 128x128x32, 8 warps (2x4), warp tile 64x32 of m16n8k16.
// Smem rows padded to 80B -> conflict-free ldmatrix, no swizzle.
// EPI=0: C[m, Nfull].  EPI=1: scatter to g_Q/g_K/g_V ([b,h,t,d]).
// ---------------------------------------------------------------------------
#define RB 80                          // bytes per 32-element bf16 row (padded)
#define TILE_B (128*RB)                // 10240 bytes per operand per buffer

template<int EPI>
__global__ __launch_bounds__(256)
void hmma_gemm(const __nv_bfloat16* __restrict__ Ah, const __nv_bfloat16* __restrict__ Al,
               const __nv_bfloat16* __restrict__ Bh, const __nv_bfloat16* __restrict__ Bl,
               float* __restrict__ C, int K, int Nfull)
{
    __shared__ __align__(16) char smem[4 * TILE_B];   // A0 A1 B0 B1

    const int tid  = threadIdx.x;
    const int lane = tid & 31;
    const int wid  = tid >> 5;
    const int wM   = wid >> 2;          // 0..1
    const int wN   = wid & 3;           // 0..3
    const int bm = blockIdx.y * 128;
    const int bn = blockIdx.x * 128;
    const int KCH = K >> 5;             // 32-wide chunks per pass
    const int NC  = 3 * KCH;

    const uint32_t sb = s2u(smem);
    const uint32_t sA = sb;
    const uint32_t sB = sb + 2 * TILE_B;

    float acc[4][4][4];
    #pragma unroll
    for (int i = 0; i < 4; i++)
        #pragma unroll
        for (int j = 0; j < 4; j++)
            #pragma unroll
            for (int q = 0; q < 4; q++) acc[i][j][q] = 0.0f;

    // ldmatrix lane-offset tables (byte offsets within an operand buffer)
    uint32_t aoff[4][2], boff[2][2];
    {
        int rA = ((lane >> 3) & 1) * 8 + (lane & 7);   // row within 16-row tile
        int cA = (lane >> 4) & 1;                      // k-half
        #pragma unroll
        for (int i = 0; i < 4; i++)
            #pragma unroll
            for (int ks = 0; ks < 2; ks++)
                aoff[i][ks] = (uint32_t)((wM*64 + i*16 + rA) * RB + (ks*2 + cA) * 16);
        int rB = lane & 15;
        int cB = (lane >> 4) & 1;
        #pragma unroll
        for (int j2 = 0; j2 < 2; j2++)
            #pragma unroll
            for (int ks = 0; ks < 2; ks++)
                boff[j2][ks] = (uint32_t)((wN*32 + j2*16 + rB) * RB + (ks*2 + cB) * 16);
    }

    auto prefetch = [&](int c, int buf){
        int phase = c / KCH;
        int kc = (c - phase * KCH) << 5;
        const __nv_bfloat16* As = (phase < 2)  ? Ah : Al;
        const __nv_bfloat16* Bs = (phase == 1) ? Bl : Bh;
        uint32_t ab = sA + buf * TILE_B;
        uint32_t bb = sB + buf * TILE_B;
        #pragma unroll
        for (int v = 0; v < 2; v++){
            int idx = tid + v * 256;        // 0..511
            int row = idx >> 2;             // 0..127
            int ch  = idx & 3;              // 16B chunk
            cp16(ab + row * RB + ch * 16, As + (size_t)(bm + row) * K + kc + ch * 8);
            cp16(bb + row * RB + ch * 16, Bs + (size_t)(bn + row) * K + kc + ch * 8);
        }
        asm volatile("cp.async.commit_group;" ::: "memory");
    };

    prefetch(0, 0);
    for (int c = 0; c < NC; c++){
        int buf = c & 1;
        if (c + 1 < NC){
            prefetch(c + 1, buf ^ 1);
            asm volatile("cp.async.wait_group 1;" ::: "memory");
        } else {
            asm volatile("cp.async.wait_group 0;" ::: "memory");
        }
        __syncthreads();

        uint32_t ab = sA + buf * TILE_B;
        uint32_t bb = sB + buf * TILE_B;
        #pragma unroll
        for (int ks = 0; ks < 2; ks++){
            uint32_t a[4][4];
            #pragma unroll
            for (int i = 0; i < 4; i++) ldmx4(a[i], ab + aoff[i][ks]);
            uint32_t br[2][4];
            #pragma unroll
            for (int j2 = 0; j2 < 2; j2++) ldmx4(br[j2], bb + boff[j2][ks]);
            uint32_t b[4][2];
            #pragma unroll
            for (int j2 = 0; j2 < 2; j2++){
                b[j2*2+0][0] = br[j2][0]; b[j2*2+0][1] = br[j2][2];
                b[j2*2+1][0] = br[j2][1]; b[j2*2+1][1] = br[j2][3];
            }
            #pragma unroll
            for (int i = 0; i < 4; i++)
                #pragma unroll
                for (int j = 0; j < 4; j++)
                    mma16816(acc[i][j], a[i], b[j]);
        }
        __syncthreads();
    }

    // Epilogue
    const int g  = lane >> 2;
    const int tg = lane & 3;
    #pragma unroll
    for (int i = 0; i < 4; i++){
        #pragma unroll
        for (int j = 0; j < 4; j++){
            int col = bn + wN*32 + j*8 + tg*2;
            #pragma unroll
            for (int h2 = 0; h2 < 2; h2++){
                int m = bm + wM*64 + i*16 + g + h2*8;
                float2 val = make_float2(acc[i][j][h2*2], acc[i][j][h2*2+1]);
                if (EPI == 0){
                    *(float2*)(C + (size_t)m * Nfull + col) = val;
                } else {
                    int part = col >> 10;
                    int hh   = (col >> 6) & (Hq - 1);
                    int d0   = col & (Dh - 1);
                    int b    = m >> 11;
                    int t    = m & (Tq - 1);
                    float* base = (part == 0) ? g_Q : (part == 1) ? g_K : g_V;
                    *(float2*)(base + (((size_t)(b*Hq + hh) * Tq + t) * Dh + d0)) = val;
                }
            }
        }
    }
}

// ---------------------------------------------------------------------------
// RoPE in-place on g_Q, g_K ([b,h,t,d])
// ---------------------------------------------------------------------------
__global__ void rope_kernel(const float* __restrict__ cosT, const float* __restrict__ sinT)
{
    int idx  = blockIdx.x * blockDim.x + threadIdx.x;
    int lane = idx & 31;
    int row  = idx >> 5;
    int t    = row & (Tq - 1);
    size_t base = (size_t)row * Dh;

    float c0 = cosT[t * Dh + lane];
    float c1 = cosT[t * Dh + 32 + lane];
    float s0 = sinT[t * Dh + lane];
    float s1 = sinT[t * Dh + 32 + lane];

    float q0 = g_Q[base + lane], q1 = g_Q[base + 32 + lane];
    g_Q[base + lane]      = q0 * c0 - q1 * s0;
    g_Q[base + 32 + lane] = q1 * c1 + q0 * s1;

    float k0 = g_K[base + lane], k1 = g_K[base + 32 + lane];
    g_K[base + lane]      = k0 * c0 - k1 * s0;
    g_K[base + 32 + lane] = k1 * c1 + k0 * s1;
}

// ---------------------------------------------------------------------------
// Flash attention (causal), fp32 FFMA. O written in [b,t,h,d].
// ---------------------------------------------------------------------------
#define PADT 68
#define FLASH_SMEM ((2 * 64 * PADT + 64 * 64) * 4)

__global__ __launch_bounds__(256)
void flash_kernel()
{
    extern __shared__ __align__(16) float sm[];
    float* Qs  = sm;
    float* KPs = sm + 64 * PADT;
    float* Vs  = sm + 2 * 64 * PADT;

    const int tid = threadIdx.x;
    const int tx = tid & 15;
    const int ty = tid >> 4;
    const int qt = blockIdx.x;
    const int bh = blockIdx.y;

    const float* Qg = g_Q + (size_t)bh * Tq * Dh + (size_t)qt * 64 * Dh;
    const float* Kg = g_K + (size_t)bh * Tq * Dh;
    const float* Vg = g_V + (size_t)bh * Tq * Dh;

    #pragma unroll
    for (int v = 0; v < 4; v++) {
        int lin = tid + v * 256;
        int row = lin >> 4;
        int c4  = (lin & 15) << 2;
        float4 q = *(const float4*)(Qg + row * Dh + c4);
        Qs[(c4 + 0) * PADT + row] = q.x * 0.125f;
        Qs[(c4 + 1) * PADT + row] = q.y * 0.125f;
        Qs[(c4 + 2) * PADT + row] = q.z * 0.125f;
        Qs[(c4 + 3) * PADT + row] = q.w * 0.125f;
    }

    float m[4], l[4], o[4][4];
    #pragma unroll
    for (int i = 0; i < 4; i++) {
        m[i] = -1e30f; l[i] = 0.0f;
        #pragma unroll
        for (int j = 0; j < 4; j++) o[i][j] = 0.0f;
    }

    for (int kt = 0; kt <= qt; kt++) {
        __syncthreads();
        const float* Kt = Kg + (size_t)kt * 64 * Dh;
        const float* Vt = Vg + (size_t)kt * 64 * Dh;
        #pragma unroll
        for (int v = 0; v < 4; v++) {
            int lin = tid + v * 256;
            int row = lin >> 4;
            int c4  = (lin & 15) << 2;
            float4 k4 = *(const float4*)(Kt + row * Dh + c4);
            KPs[(c4 + 0) * PADT + row] = k4.x;
            KPs[(c4 + 1) * PADT + row] = k4.y;
            KPs[(c4 + 2) * PADT + row] = k4.z;
            KPs[(c4 + 3) * PADT + row] = k4.w;
            float4 v4 = *(const float4*)(Vt + row * Dh + c4);
            *(float4*)(Vs + row * Dh + c4) = v4;
        }
        __syncthreads();

        float s[4][4];
        #pragma unroll
        for (int i = 0; i < 4; i++)
            #pragma unroll
            for (int j = 0; j < 4; j++) s[i][j] = 0.0f;

        #pragma unroll 8
        for (int d = 0; d < 64; d++) {
            float a[4], b[4];
            *(float4*)a = *(const float4*)&Qs[d * PADT + ty * 4];
            *(float4*)b = *(const float4*)&KPs[d * PADT + tx * 4];
            #pragma unroll
            for (int i = 0; i < 4; i++)
                #pragma unroll
                for (int j = 0; j < 4; j++)
                    s[i][j] = fmaf(a[i], b[j], s[i][j]);
        }

        if (kt == qt) {
            #pragma unroll
            for (int i = 0; i < 4; i++)
                #pragma unroll
                for (int j = 0; j < 4; j++)
                    if (tx * 4 + j > ty * 4 + i) s[i][j] = -1e30f;
        }

        __syncthreads();

        #pragma unroll
        for (int i = 0; i < 4; i++) {
            float mx = fmaxf(fmaxf(s[i][0], s[i][1]), fmaxf(s[i][2], s[i][3]));
            mx = fmaxf(mx, __shfl_xor_sync(0xffffffffu, mx, 1));
            mx = fmaxf(mx, __shfl_xor_sync(0xffffffffu, mx, 2));
            mx = fmaxf(mx, __shfl_xor_sync(0xffffffffu, mx, 4));
            mx = fmaxf(mx, __shfl_xor_sync(0xffffffffu, mx, 8));
            float mn = fmaxf(m[i], mx);
            float alpha = __expf(m[i] - mn);
            m[i] = mn;
            float p0 = __expf(s[i][0] - mn);
            float p1 = __expf(s[i][1] - mn);
            float p2 = __expf(s[i][2] - mn);
            float p3 = __expf(s[i][3] - mn);
            float rs = (p0 + p1) + (p2 + p3);
            rs += __shfl_xor_sync(0xffffffffu, rs, 1);
            rs += __shfl_xor_sync(0xffffffffu, rs, 2);
            rs += __shfl_xor_sync(0xffffffffu, rs, 4);
            rs += __shfl_xor_sync(0xffffffffu, rs, 8);
            l[i] = l[i] * alpha + rs;
            #pragma unroll
            for (int j = 0; j < 4; j++) o[i][j] *= alpha;
            *(float4*)&KPs[(ty * 4 + i) * 64 + tx * 4] = make_float4(p0, p1, p2, p3);
        }
        __syncthreads();

        #pragma unroll 8
        for (int k = 0; k < 64; k++) {
            float vv[4];
            *(float4*)vv = *(const float4*)&Vs[k * Dh + tx * 4];
            #pragma unroll
            for (int i = 0; i < 4; i++) {
                float p = KPs[(ty * 4 + i) * 64 + k];
                #pragma unroll
                for (int j = 0; j < 4; j++)
                    o[i][j] = fmaf(p, vv[j], o[i][j]);
            }
        }
    }

    // O in [b, t, h, d]
    int b = bh >> 4, h = bh & (Hq - 1);
    float* Og = g_O + (((size_t)b * Tq + (size_t)qt * 64) * Hq + h) * Dh;
    #pragma unroll
    for (int i = 0; i < 4; i++) {
        float inv = 1.0f / l[i];
        *(float4*)(Og + (size_t)(ty * 4 + i) * (Hq * Dh) + tx * 4) =
            make_float4(o[i][0] * inv, o[i][1] * inv, o[i][2] * inv, o[i][3] * inv);
    }
}

// ---------------------------------------------------------------------------
extern "C" void kernel_launch(void* const* d_in, const int* in_sizes, int n_in,
                              void* d_out, int out_size)
{
    (void)in_sizes; (void)n_in; (void)out_size;
    const float* x     = (const float*)d_in[0];
    const float* cosT  = (const float*)d_in[1];
    const float* sinT  = (const float*)d_in[2];
    const float* w_qkv = (const float*)d_in[3];
    const float* w_out = (const float*)d_in[4];
    float* out = (float*)d_out;

    void *p_xh, *p_xl, *p_wqh, *p_wql, *p_woh, *p_wol, *p_oh, *p_ol, *p_O;
    cudaGetSymbolAddress(&p_xh,  g_x_hi);  cudaGetSymbolAddress(&p_xl,  g_x_lo);
    cudaGetSymbolAddress(&p_wqh, g_wq_hi); cudaGetSymbolAddress(&p_wql, g_wq_lo);
    cudaGetSymbolAddress(&p_woh, g_wo_hi); cudaGetSymbolAddress(&p_wol, g_wo_lo);
    cudaGetSymbolAddress(&p_oh,  g_o_hi);  cudaGetSymbolAddress(&p_ol,  g_o_lo);
    cudaGetSymbolAddress(&p_O,   g_O);

    cudaFuncSetAttribute(flash_kernel, cudaFuncAttributeMaxDynamicSharedMemorySize, FLASH_SMEM);

    // 1) fp32 -> bf16 hi/lo splits of x and weights
    split_kernel<<<(MROWS*Cq/4 + 255)/256, 256>>>(x, (__nv_bfloat16*)p_xh, (__nv_bfloat16*)p_xl, MROWS*Cq/4);
    split_kernel<<<(3*Cq*Cq/4 + 255)/256, 256>>>(w_qkv, (__nv_bfloat16*)p_wqh, (__nv_bfloat16*)p_wql, 3*Cq*Cq/4);
    split_kernel<<<(Cq*Cq/4 + 255)/256, 256>>>(w_out, (__nv_bfloat16*)p_woh, (__nv_bfloat16*)p_wol, Cq*Cq/4);

    // 2) QKV projection (HMMA, 3-pass), scatter into g_Q/g_K/g_V
    {
        dim3 grid(3*Cq / 128, MROWS / 128);   // (24, 64)
        hmma_gemm<1><<<grid, 256>>>((const __nv_bfloat16*)p_xh, (const __nv_bfloat16*)p_xl,
                                    (const __nv_bfloat16*)p_wqh, (const __nv_bfloat16*)p_wql,
                                    nullptr, Cq, 3*Cq);
    }
    // 3) RoPE
    rope_kernel<<<(Bq*Hq*Tq*32)/256, 256>>>(cosT, sinT);

    // 4) Causal flash attention (fp32)
    {
        dim3 grid(Tq / 64, Bq * Hq);
        flash_kernel<<<grid, 256, FLASH_SMEM>>>();
    }

    // 5) Split O, 6) output projection (HMMA, 3-pass)
    split_kernel<<<(MROWS*Cq/4 + 255)/256, 256>>>((const float*)p_O, (__nv_bfloat16*)p_oh, (__nv_bfloat16*)p_ol, MROWS*Cq/4);
    {
        dim3 grid(Cq / 128, MROWS / 128);     // (8, 64)
        hmma_gemm<0><<<grid, 256>>>((const __nv_bfloat16*)p_oh, (const __nv_bfloat16*)p_ol,
                                    (const __nv_bfloat16*)p_woh, (const __nv_bfloat16*)p_wol,
                                    out, Cq, Cq);
    }
}

// round 4
// speedup vs baseline: 2.4220x; 1.6945x over previous
#include <cuda_runtime.h>
#include <cuda_bf16.h>
#include <cuda_fp16.h>
#include <cstdint>

#define Bq 4
#define Tq 2048
#define Cq 1024
#define Hq 16
#define Dh 64
#define MROWS (Bq*Tq)          // 8192
#define NHTD (Bq*Hq*Tq*Dh)     // 8,388,608

// ---------------------------------------------------------------------------
// Device-global scratch
// ---------------------------------------------------------------------------
__device__ float g_Q[NHTD];              // [b,h,t,d] fp32 (pre-rope)
__device__ float g_K[NHTD];              // [b,h,t,d] fp32 (pre-rope)
__device__ __nv_bfloat16 g_q_hi[NHTD], g_q_lo[NHTD];   // post-rope, scaled log2e/8
__device__ __nv_bfloat16 g_k_hi[NHTD], g_k_lo[NHTD];   // post-rope
__device__ __half        g_v_hi[NHTD], g_v_lo[NHTD];   // [b,h,t,d]

__device__ __nv_bfloat16 g_x_hi[MROWS*Cq],  g_x_lo[MROWS*Cq];
__device__ __nv_bfloat16 g_wq_hi[3*Cq*Cq],  g_wq_lo[3*Cq*Cq];
__device__ __nv_bfloat16 g_wo_hi[Cq*Cq],    g_wo_lo[Cq*Cq];
__device__ __nv_bfloat16 g_o_hi[MROWS*Cq],  g_o_lo[MROWS*Cq];   // [b,t,h,d]

// ---------------------------------------------------------------------------
// helpers
// ---------------------------------------------------------------------------
__device__ __forceinline__ uint32_t s2u(const void* p){
    uint32_t a;
    asm("{ .reg .u64 t; cvta.to.shared.u64 t, %1; cvt.u32.u64 %0, t; }" : "=r"(a) : "l"(p));
    return a;
}
__device__ __forceinline__ void cp16(uint32_t dst, const void* src){
    asm volatile("cp.async.cg.shared.global [%0], [%1], 16;" :: "r"(dst), "l"(src));
}
__device__ __forceinline__ void ldmx4(uint32_t* r, uint32_t addr){
    asm volatile("ldmatrix.sync.aligned.m8n8.x4.shared.b16 {%0,%1,%2,%3}, [%4];"
                 : "=r"(r[0]), "=r"(r[1]), "=r"(r[2]), "=r"(r[3]) : "r"(addr));
}
__device__ __forceinline__ void ldmx4t(uint32_t* r, uint32_t addr){
    asm volatile("ldmatrix.sync.aligned.m8n8.x4.trans.shared.b16 {%0,%1,%2,%3}, [%4];"
                 : "=r"(r[0]), "=r"(r[1]), "=r"(r[2]), "=r"(r[3]) : "r"(addr));
}
__device__ __forceinline__ void mma_bf(float* c, const uint32_t* a, const uint32_t* b){
    asm volatile(
        "mma.sync.aligned.m16n8k16.row.col.f32.bf16.bf16.f32 "
        "{%0,%1,%2,%3}, {%4,%5,%6,%7}, {%8,%9}, {%0,%1,%2,%3};"
        : "+f"(c[0]), "+f"(c[1]), "+f"(c[2]), "+f"(c[3])
        : "r"(a[0]), "r"(a[1]), "r"(a[2]), "r"(a[3]), "r"(b[0]), "r"(b[1]));
}
__device__ __forceinline__ void mma_f16(float* c, const uint32_t* a, const uint32_t* b){
    asm volatile(
        "mma.sync.aligned.m16n8k16.row.col.f32.f16.f16.f32 "
        "{%0,%1,%2,%3}, {%4,%5,%6,%7}, {%8,%9}, {%0,%1,%2,%3};"
        : "+f"(c[0]), "+f"(c[1]), "+f"(c[2]), "+f"(c[3])
        : "r"(a[0]), "r"(a[1]), "r"(a[2]), "r"(a[3]), "r"(b[0]), "r"(b[1]));
}
__device__ __forceinline__ uint32_t cvt_f16x2(float lo, float hi){
    uint32_t r;
    asm("cvt.rn.f16x2.f32 %0, %1, %2;" : "=r"(r) : "f"(hi), "f"(lo));
    return r;
}
__device__ __forceinline__ uint32_t ex2_f16x2(uint32_t x){
    uint32_t r;
    asm("ex2.approx.f16x2 %0, %1;" : "=r"(r) : "r"(x));
    return r;
}
__device__ __forceinline__ float ex2f(float x){
    float r;
    asm("ex2.approx.ftz.f32 %0, %1;" : "=f"(r) : "f"(x));
    return r;
}

// ---------------------------------------------------------------------------
// fp32 -> (bf16 hi, bf16 lo) split
// ---------------------------------------------------------------------------
__global__ void split_kernel(const float* __restrict__ src,
                             __nv_bfloat16* __restrict__ hi,
                             __nv_bfloat16* __restrict__ lo, int n4)
{
    int i = blockIdx.x * blockDim.x + threadIdx.x;
    if (i >= n4) return;
    float4 v = ((const float4*)src)[i];
    __nv_bfloat16 h0 = __float2bfloat16(v.x);
    __nv_bfloat16 h1 = __float2bfloat16(v.y);
    __nv_bfloat16 h2 = __float2bfloat16(v.z);
    __nv_bfloat16 h3 = __float2bfloat16(v.w);
    __nv_bfloat16 l0 = __float2bfloat16(v.x - __bfloat162float(h0));
    __nv_bfloat16 l1 = __float2bfloat16(v.y - __bfloat162float(h1));
    __nv_bfloat16 l2 = __float2bfloat16(v.z - __bfloat162float(h2));
    __nv_bfloat16 l3 = __float2bfloat16(v.w - __bfloat162float(h3));
    ((__nv_bfloat162*)hi)[2*i]   = __halves2bfloat162(h0, h1);
    ((__nv_bfloat162*)hi)[2*i+1] = __halves2bfloat162(h2, h3);
    ((__nv_bfloat162*)lo)[2*i]   = __halves2bfloat162(l0, l1);
    ((__nv_bfloat162*)lo)[2*i+1] = __halves2bfloat162(l2, l3);
}

// ---------------------------------------------------------------------------
// HMMA GEMM (unchanged core, EPI=1 epilogue writes V as f16 hi/lo)
// ---------------------------------------------------------------------------
#define RB 80
#define TILE_B (128*RB)

template<int EPI>
__global__ __launch_bounds__(256)
void hmma_gemm(const __nv_bfloat16* __restrict__ Ah, const __nv_bfloat16* __restrict__ Al,
               const __nv_bfloat16* __restrict__ Bh, const __nv_bfloat16* __restrict__ Bl,
               float* __restrict__ C, int K, int Nfull)
{
    __shared__ __align__(16) char smem[4 * TILE_B];

    const int tid  = threadIdx.x;
    const int lane = tid & 31;
    const int wid  = tid >> 5;
    const int wM   = wid >> 2;
    const int wN   = wid & 3;
    const int bm = blockIdx.y * 128;
    const int bn = blockIdx.x * 128;
    const int KCH = K >> 5;
    const int NC  = 3 * KCH;

    const uint32_t sb = s2u(smem);
    const uint32_t sA = sb;
    const uint32_t sB = sb + 2 * TILE_B;

    float acc[4][4][4];
    #pragma unroll
    for (int i = 0; i < 4; i++)
        #pragma unroll
        for (int j = 0; j < 4; j++)
            #pragma unroll
            for (int q = 0; q < 4; q++) acc[i][j][q] = 0.0f;

    uint32_t aoff[4][2], boff[2][2];
    {
        int rA = ((lane >> 3) & 1) * 8 + (lane & 7);
        int cA = (lane >> 4) & 1;
        #pragma unroll
        for (int i = 0; i < 4; i++)
            #pragma unroll
            for (int ks = 0; ks < 2; ks++)
                aoff[i][ks] = (uint32_t)((wM*64 + i*16 + rA) * RB + (ks*2 + cA) * 16);
        int rB = lane & 15;
        int cB = (lane >> 4) & 1;
        #pragma unroll
        for (int j2 = 0; j2 < 2; j2++)
            #pragma unroll
            for (int ks = 0; ks < 2; ks++)
                boff[j2][ks] = (uint32_t)((wN*32 + j2*16 + rB) * RB + (ks*2 + cB) * 16);
    }

    auto prefetch = [&](int c, int buf){
        int phase = c / KCH;
        int kc = (c - phase * KCH) << 5;
        const __nv_bfloat16* As = (phase < 2)  ? Ah : Al;
        const __nv_bfloat16* Bs = (phase == 1) ? Bl : Bh;
        uint32_t ab = sA + buf * TILE_B;
        uint32_t bb = sB + buf * TILE_B;
        #pragma unroll
        for (int v = 0; v < 2; v++){
            int idx = tid + v * 256;
            int row = idx >> 2;
            int ch  = idx & 3;
            cp16(ab + row * RB + ch * 16, As + (size_t)(bm + row) * K + kc + ch * 8);
            cp16(bb + row * RB + ch * 16, Bs + (size_t)(bn + row) * K + kc + ch * 8);
        }
        asm volatile("cp.async.commit_group;" ::: "memory");
    };

    prefetch(0, 0);
    for (int c = 0; c < NC; c++){
        int buf = c & 1;
        if (c + 1 < NC){
            prefetch(c + 1, buf ^ 1);
            asm volatile("cp.async.wait_group 1;" ::: "memory");
        } else {
            asm volatile("cp.async.wait_group 0;" ::: "memory");
        }
        __syncthreads();

        uint32_t ab = sA + buf * TILE_B;
        uint32_t bb = sB + buf * TILE_B;
        #pragma unroll
        for (int ks = 0; ks < 2; ks++){
            uint32_t a[4][4];
            #pragma unroll
            for (int i = 0; i < 4; i++) ldmx4(a[i], ab + aoff[i][ks]);
            uint32_t br[2][4];
            #pragma unroll
            for (int j2 = 0; j2 < 2; j2++) ldmx4(br[j2], bb + boff[j2][ks]);
            uint32_t b[4][2];
            #pragma unroll
            for (int j2 = 0; j2 < 2; j2++){
                b[j2*2+0][0] = br[j2][0]; b[j2*2+0][1] = br[j2][2];
                b[j2*2+1][0] = br[j2][1]; b[j2*2+1][1] = br[j2][3];
            }
            #pragma unroll
            for (int i = 0; i < 4; i++)
                #pragma unroll
                for (int j = 0; j < 4; j++)
                    mma_bf(acc[i][j], a[i], b[j]);
        }
        __syncthreads();
    }

    const int g  = lane >> 2;
    const int tg = lane & 3;
    #pragma unroll
    for (int i = 0; i < 4; i++){
        #pragma unroll
        for (int j = 0; j < 4; j++){
            int col = bn + wN*32 + j*8 + tg*2;
            #pragma unroll
            for (int h2 = 0; h2 < 2; h2++){
                int m = bm + wM*64 + i*16 + g + h2*8;
                float2 val = make_float2(acc[i][j][h2*2], acc[i][j][h2*2+1]);
                if (EPI == 0){
                    *(float2*)(C + (size_t)m * Nfull + col) = val;
                } else {
                    int part = col >> 10;
                    int hh   = (col >> 6) & (Hq - 1);
                    int d0   = col & (Dh - 1);
                    int b    = m >> 11;
                    int t    = m & (Tq - 1);
                    size_t idx = ((size_t)(b*Hq + hh) * Tq + t) * Dh + d0;
                    if (part == 2){
                        __half h0 = __float2half_rn(val.x);
                        __half h1 = __float2half_rn(val.y);
                        __half l0 = __float2half_rn(val.x - __half2float(h0));
                        __half l1 = __float2half_rn(val.y - __half2float(h1));
                        *(__half2*)(g_v_hi + idx) = __halves2half2(h0, h1);
                        *(__half2*)(g_v_lo + idx) = __halves2half2(l0, l1);
                    } else {
                        float* base = (part == 0) ? g_Q : g_K;
                        *(float2*)(base + idx) = val;
                    }
                }
            }
        }
    }
}

// ---------------------------------------------------------------------------
// RoPE: read g_Q/g_K fp32, write bf16 hi/lo (Q scaled by log2e/8)
// ---------------------------------------------------------------------------
#define QSC 0.18033688011112042f   // log2(e)/8

__global__ void rope_kernel(const float* __restrict__ cosT, const float* __restrict__ sinT)
{
    int idx  = blockIdx.x * blockDim.x + threadIdx.x;
    int lane = idx & 31;
    int row  = idx >> 5;
    int t    = row & (Tq - 1);
    size_t base = (size_t)row * Dh;

    float c0 = cosT[t * Dh + lane];
    float c1 = cosT[t * Dh + 32 + lane];
    float s0 = sinT[t * Dh + lane];
    float s1 = sinT[t * Dh + 32 + lane];

    float q0 = g_Q[base + lane], q1 = g_Q[base + 32 + lane];
    float qa = (q0 * c0 - q1 * s0) * QSC;
    float qb = (q1 * c1 + q0 * s1) * QSC;
    __nv_bfloat16 ha = __float2bfloat16(qa);
    __nv_bfloat16 hb = __float2bfloat16(qb);
    g_q_hi[base + lane]      = ha;
    g_q_hi[base + 32 + lane] = hb;
    g_q_lo[base + lane]      = __float2bfloat16(qa - __bfloat162float(ha));
    g_q_lo[base + 32 + lane] = __float2bfloat16(qb - __bfloat162float(hb));

    float k0 = g_K[base + lane], k1 = g_K[base + 32 + lane];
    float ka = k0 * c0 - k1 * s0;
    float kb = k1 * c1 + k0 * s1;
    __nv_bfloat16 hka = __float2bfloat16(ka);
    __nv_bfloat16 hkb = __float2bfloat16(kb);
    g_k_hi[base + lane]      = hka;
    g_k_hi[base + 32 + lane] = hkb;
    g_k_lo[base + lane]      = __float2bfloat16(ka - __bfloat162float(hka));
    g_k_lo[base + 32 + lane] = __float2bfloat16(kb - __bfloat162float(hkb));
}

// ---------------------------------------------------------------------------
// Tensor-core flash attention (causal).
// CTA = 128 q-rows, 8 warps x 16 rows. k-blocks of 64, double-buffered.
// S: 3-pass bf16 hi/lo. P: f16 via ex2.f16x2. PV: 2-pass f16 V hi/lo.
// Row sums: P @ ones via MMA (fp32-exact). Output: bf16 hi/lo [b,t,h,d].
// ---------------------------------------------------------------------------
#define FS_Q 0            // Qh @0, Ql @16384   (32768 total)
#define FS_K 32768        // buf b: +b*16384; Kh +0, Kl +8192
#define FS_V 65536        // buf b: +b*16384; Vh +0, Vl +8192
#define FLASH_SMEM 98304

__global__ __launch_bounds__(256)
void flash_tc()
{
    extern __shared__ __align__(1024) char fsm[];
    const uint32_t sb = s2u(fsm);
    const int tid  = threadIdx.x;
    const int lane = tid & 31;
    const int w    = tid >> 5;
    const int qt   = (int)(gridDim.x - 1 - blockIdx.x);  // heavy tiles first
    const int bh   = blockIdx.y;
    const int b    = bh >> 4, h = bh & (Hq - 1);
    const int nkb  = 2 * qt + 2;

    // ---- load Q tile (hi+lo), swizzled 128B rows ----
    {
        const __nv_bfloat16* qh = g_q_hi + ((size_t)bh * Tq + (size_t)qt * 128) * Dh;
        const __nv_bfloat16* ql = g_q_lo + ((size_t)bh * Tq + (size_t)qt * 128) * Dh;
        #pragma unroll
        for (int v = 0; v < 4; v++){
            int idx = tid + v * 256;          // 0..1023
            int row = idx >> 3;               // 0..127
            int c   = idx & 7;
            uint32_t sw = (uint32_t)(row * 128 + ((c ^ (row & 7)) << 4));
            cp16(sb + FS_Q + sw,         qh + (size_t)row * Dh + c * 8);
            cp16(sb + FS_Q + 16384 + sw, ql + (size_t)row * Dh + c * 8);
        }
    }

    auto prefetch = [&](int kt, int buf){
        size_t off = ((size_t)bh * Tq + (size_t)kt * 64) * Dh;
        const __nv_bfloat16* kh = g_k_hi + off;
        const __nv_bfloat16* kl = g_k_lo + off;
        const __half* vh = g_v_hi + off;
        const __half* vl = g_v_lo + off;
        #pragma unroll
        for (int v = 0; v < 2; v++){
            int idx = tid + v * 256;          // 0..511
            int row = idx >> 3;               // 0..63
            int c   = idx & 7;
            uint32_t sw = (uint32_t)(row * 128 + ((c ^ (row & 7)) << 4));
            cp16(sb + FS_K + buf*16384 + sw,        kh + (size_t)row * Dh + c * 8);
            cp16(sb + FS_K + buf*16384 + 8192 + sw, kl + (size_t)row * Dh + c * 8);
            cp16(sb + FS_V + buf*16384 + sw,        vh + (size_t)row * Dh + c * 8);
            cp16(sb + FS_V + buf*16384 + 8192 + sw, vl + (size_t)row * Dh + c * 8);
        }
        asm volatile("cp.async.commit_group;" ::: "memory");
    };

    prefetch(0, 0);   // committed together with Q loads above

    float sO[8][4];
    #pragma unroll
    for (int i = 0; i < 8; i++)
        #pragma unroll
        for (int q = 0; q < 4; q++) sO[i][q] = 0.0f;
    float lac[4] = {0.f, 0.f, 0.f, 0.f};
    float m0 = -1e30f, m1 = -1e30f;

    const int rA = ((lane >> 3) & 1) * 8 + (lane & 7);
    const int cA = (lane >> 4) & 1;
    const int rB = lane & 15;
    const int cB = lane >> 4;
    const int qrow = w * 16 + rA;
    const uint32_t ONE2 = 0x3C003C00u;
    const uint32_t ob[2] = {ONE2, ONE2};

    for (int kt = 0; kt < nkb; kt++){
        int buf = kt & 1;
        if (kt + 1 < nkb){
            prefetch(kt + 1, buf ^ 1);
            asm volatile("cp.async.wait_group 1;" ::: "memory");
        } else {
            asm volatile("cp.async.wait_group 0;" ::: "memory");
        }
        __syncthreads();

        bool skip = (kt == 2*qt + 1) && (w < 4);   // fully-masked block for lower warps
        if (!skip){
            // ---- S = Q @ K^T, 3 passes (HH, LH, HL) ----
            float s[8][4];
            #pragma unroll
            for (int i = 0; i < 8; i++)
                #pragma unroll
                for (int q = 0; q < 4; q++) s[i][q] = 0.0f;

            #pragma unroll
            for (int pass = 0; pass < 3; pass++){
                uint32_t qb = sb + FS_Q + (pass == 1 ? 16384 : 0);
                uint32_t kbse = sb + FS_K + buf*16384 + (pass == 2 ? 8192 : 0);
                #pragma unroll
                for (int ks = 0; ks < 4; ks++){
                    uint32_t a[4];
                    ldmx4(a, qb + qrow*128 + (((ks*2 + cA) ^ (qrow & 7)) << 4));
                    #pragma unroll
                    for (int j2 = 0; j2 < 4; j2++){
                        int krow = j2*16 + rB;
                        uint32_t br[4];
                        ldmx4(br, kbse + krow*128 + (((ks*2 + cB) ^ (krow & 7)) << 4));
                        uint32_t b0[2] = {br[0], br[2]};
                        uint32_t b1[2] = {br[1], br[3]};
                        mma_bf(s[j2*2],     a, b0);
                        mma_bf(s[j2*2 + 1], a, b1);
                    }
                }
            }

            // ---- causal mask (diagonal region only) ----
            if (kt >= 2*qt){
                int co = (kt - 2*qt) * 64;
                int lr0 = w*16 + (lane >> 2);
                int lr1 = lr0 + 8;
                #pragma unroll
                for (int nt = 0; nt < 8; nt++){
                    int c0 = co + nt*8 + (lane & 3)*2;
                    if (c0     > lr0) s[nt][0] = -1e30f;
                    if (c0 + 1 > lr0) s[nt][1] = -1e30f;
                    if (c0     > lr1) s[nt][2] = -1e30f;
                    if (c0 + 1 > lr1) s[nt][3] = -1e30f;
                }
            }

            // ---- online softmax (base-2 domain) ----
            float mx0 = -1e30f, mx1 = -1e30f;
            #pragma unroll
            for (int nt = 0; nt < 8; nt++){
                mx0 = fmaxf(mx0, fmaxf(s[nt][0], s[nt][1]));
                mx1 = fmaxf(mx1, fmaxf(s[nt][2], s[nt][3]));
            }
            mx0 = fmaxf(mx0, __shfl_xor_sync(0xffffffffu, mx0, 1));
            mx0 = fmaxf(mx0, __shfl_xor_sync(0xffffffffu, mx0, 2));
            mx1 = fmaxf(mx1, __shfl_xor_sync(0xffffffffu, mx1, 1));
            mx1 = fmaxf(mx1, __shfl_xor_sync(0xffffffffu, mx1, 2));
            float mn0 = fmaxf(m0, mx0), mn1 = fmaxf(m1, mx1);
            float al0 = ex2f(m0 - mn0), al1 = ex2f(m1 - mn1);
            m0 = mn0; m1 = mn1;
            #pragma unroll
            for (int nt = 0; nt < 8; nt++){
                sO[nt][0] *= al0; sO[nt][1] *= al0;
                sO[nt][2] *= al1; sO[nt][3] *= al1;
            }
            lac[0] *= al0; lac[1] *= al0; lac[2] *= al1; lac[3] *= al1;

            // ---- P = 2^(s-m) in f16x2, laid out as PV A-fragments ----
            uint32_t P[8][2];
            #pragma unroll
            for (int nt = 0; nt < 8; nt++){
                P[nt][0] = ex2_f16x2(cvt_f16x2(s[nt][0] - mn0, s[nt][1] - mn0));
                P[nt][1] = ex2_f16x2(cvt_f16x2(s[nt][2] - mn1, s[nt][3] - mn1));
            }

            // ---- row sums: lac += P @ ones ----
            #pragma unroll
            for (int ks = 0; ks < 4; ks++){
                uint32_t a[4] = {P[2*ks][0], P[2*ks][1], P[2*ks+1][0], P[2*ks+1][1]};
                mma_f16(lac, a, ob);
            }

            // ---- O += P @ V (2 passes: Vh, Vl) ----
            #pragma unroll
            for (int pass = 0; pass < 2; pass++){
                uint32_t vb = sb + FS_V + buf*16384 + pass*8192;
                #pragma unroll
                for (int ks = 0; ks < 4; ks++){
                    uint32_t a[4] = {P[2*ks][0], P[2*ks][1], P[2*ks+1][0], P[2*ks+1][1]};
                    #pragma unroll
                    for (int dt2 = 0; dt2 < 4; dt2++){
                        int vrow = ks*16 + (lane & 15);
                        int chnk = dt2*2 + (lane >> 4);
                        uint32_t br[4];
                        ldmx4t(br, vb + vrow*128 + ((chnk ^ (vrow & 7)) << 4));
                        uint32_t b0[2] = {br[0], br[1]};
                        uint32_t b1[2] = {br[2], br[3]};
                        mma_f16(sO[dt2*2],     a, b0);
                        mma_f16(sO[dt2*2 + 1], a, b1);
                    }
                }
            }
        }
        __syncthreads();
    }

    // ---- epilogue: normalize, write bf16 hi/lo at [b,t,h,d] ----
    float inv0 = 1.0f / lac[0];
    float inv1 = 1.0f / lac[2];
    int tr0 = qt*128 + w*16 + (lane >> 2);
    int tr1 = tr0 + 8;
    #pragma unroll
    for (int dt = 0; dt < 8; dt++){
        int d = dt*8 + (lane & 3)*2;
        float v00 = sO[dt][0] * inv0, v01 = sO[dt][1] * inv0;
        float v10 = sO[dt][2] * inv1, v11 = sO[dt][3] * inv1;
        size_t i0 = ((size_t)(b * Tq + tr0) * Hq + h) * Dh + d;
        size_t i1 = ((size_t)(b * Tq + tr1) * Hq + h) * Dh + d;
        __nv_bfloat16 h00 = __float2bfloat16(v00), h01 = __float2bfloat16(v01);
        __nv_bfloat16 h10 = __float2bfloat16(v10), h11 = __float2bfloat16(v11);
        *(__nv_bfloat162*)(g_o_hi + i0) = __halves2bfloat162(h00, h01);
        *(__nv_bfloat162*)(g_o_hi + i1) = __halves2bfloat162(h10, h11);
        *(__nv_bfloat162*)(g_o_lo + i0) = __halves2bfloat162(
            __float2bfloat16(v00 - __bfloat162float(h00)),
            __float2bfloat16(v01 - __bfloat162float(h01)));
        *(__nv_bfloat162*)(g_o_lo + i1) = __halves2bfloat162(
            __float2bfloat16(v10 - __bfloat162float(h10)),
            __float2bfloat16(v11 - __bfloat162float(h11)));
    }
}

// ---------------------------------------------------------------------------
extern "C" void kernel_launch(void* const* d_in, const int* in_sizes, int n_in,
                              void* d_out, int out_size)
{
    (void)in_sizes; (void)n_in; (void)out_size;
    const float* x     = (const float*)d_in[0];
    const float* cosT  = (const float*)d_in[1];
    const float* sinT  = (const float*)d_in[2];
    const float* w_qkv = (const float*)d_in[3];
    const float* w_out = (const float*)d_in[4];
    float* out = (float*)d_out;

    void *p_xh, *p_xl, *p_wqh, *p_wql, *p_woh, *p_wol, *p_oh, *p_ol;
    cudaGetSymbolAddress(&p_xh,  g_x_hi);  cudaGetSymbolAddress(&p_xl,  g_x_lo);
    cudaGetSymbolAddress(&p_wqh, g_wq_hi); cudaGetSymbolAddress(&p_wql, g_wq_lo);
    cudaGetSymbolAddress(&p_woh, g_wo_hi); cudaGetSymbolAddress(&p_wol, g_wo_lo);
    cudaGetSymbolAddress(&p_oh,  g_o_hi);  cudaGetSymbolAddress(&p_ol,  g_o_lo);

    cudaFuncSetAttribute(flash_tc, cudaFuncAttributeMaxDynamicSharedMemorySize, FLASH_SMEM);

    // 1) fp32 -> bf16 hi/lo splits of x and weights
    split_kernel<<<(MROWS*Cq/4 + 255)/256, 256>>>(x, (__nv_bfloat16*)p_xh, (__nv_bfloat16*)p_xl, MROWS*Cq/4);
    split_kernel<<<(3*Cq*Cq/4 + 255)/256, 256>>>(w_qkv, (__nv_bfloat16*)p_wqh, (__nv_bfloat16*)p_wql, 3*Cq*Cq/4);
    split_kernel<<<(Cq*Cq/4 + 255)/256, 256>>>(w_out, (__nv_bfloat16*)p_woh, (__nv_bfloat16*)p_wol, Cq*Cq/4);

    // 2) QKV projection: Q,K fp32; V straight to f16 hi/lo
    {
        dim3 grid(3*Cq / 128, MROWS / 128);
        hmma_gemm<1><<<grid, 256>>>((const __nv_bfloat16*)p_xh, (const __nv_bfloat16*)p_xl,
                                    (const __nv_bfloat16*)p_wqh, (const __nv_bfloat16*)p_wql,
                                    nullptr, Cq, 3*Cq);
    }
    // 3) RoPE -> bf16 hi/lo (Q scaled by log2e/8)
    rope_kernel<<<(Bq*Hq*Tq*32)/256, 256>>>(cosT, sinT);

    // 4) Tensor-core causal flash attention -> g_o_hi/lo
    {
        dim3 grid(Tq / 128, Bq * Hq);
        flash_tc<<<grid, 256, FLASH_SMEM>>>();
    }

    // 5) Output projection
    {
        dim3 grid(Cq / 128, MROWS / 128);
        hmma_gemm<0><<<grid, 256>>>((const __nv_bfloat16*)p_oh, (const __nv_bfloat16*)p_ol,
                                    (const __nv_bfloat16*)p_woh, (const __nv_bfloat16*)p_wol,
                                    out, Cq, Cq);
    }
}

// round 5
// speedup vs baseline: 2.7996x; 1.1559x over previous
#include <cuda_runtime.h>
#include <cuda_bf16.h>
#include <cuda_fp16.h>
#include <cstdint>

#define Bq 4
#define Tq 2048
#define Cq 1024
#define Hq 16
#define Dh 64
#define MROWS (Bq*Tq)          // 8192
#define NHTD (Bq*Hq*Tq*Dh)     // 8,388,608

// ---------------------------------------------------------------------------
// Device-global scratch
// ---------------------------------------------------------------------------
__device__ float g_Q[NHTD];              // [b,h,t,d] fp32 (pre-rope)
__device__ float g_K[NHTD];              // [b,h,t,d] fp32 (pre-rope)
__device__ __nv_bfloat16 g_q_hi[NHTD], g_q_lo[NHTD];   // post-rope, scaled log2e/8
__device__ __nv_bfloat16 g_k_hi[NHTD], g_k_lo[NHTD];   // post-rope
__device__ __half        g_v_hi[NHTD], g_v_lo[NHTD];   // [b,h,t,d]

__device__ __nv_bfloat16 g_x_hi[MROWS*Cq],  g_x_lo[MROWS*Cq];
__device__ __nv_bfloat16 g_wq_hi[3*Cq*Cq],  g_wq_lo[3*Cq*Cq];
__device__ __nv_bfloat16 g_wo_hi[Cq*Cq],    g_wo_lo[Cq*Cq];
__device__ __nv_bfloat16 g_o_hi[MROWS*Cq],  g_o_lo[MROWS*Cq];   // [b,t,h,d]

// ---------------------------------------------------------------------------
// helpers
// ---------------------------------------------------------------------------
__device__ __forceinline__ uint32_t s2u(const void* p){
    uint32_t a;
    asm("{ .reg .u64 t; cvta.to.shared.u64 t, %1; cvt.u32.u64 %0, t; }" : "=r"(a) : "l"(p));
    return a;
}
__device__ __forceinline__ void cp16(uint32_t dst, const void* src){
    asm volatile("cp.async.cg.shared.global [%0], [%1], 16;" :: "r"(dst), "l"(src));
}
__device__ __forceinline__ void ldmx4(uint32_t* r, uint32_t addr){
    asm volatile("ldmatrix.sync.aligned.m8n8.x4.shared.b16 {%0,%1,%2,%3}, [%4];"
                 : "=r"(r[0]), "=r"(r[1]), "=r"(r[2]), "=r"(r[3]) : "r"(addr));
}
__device__ __forceinline__ void ldmx4t(uint32_t* r, uint32_t addr){
    asm volatile("ldmatrix.sync.aligned.m8n8.x4.trans.shared.b16 {%0,%1,%2,%3}, [%4];"
                 : "=r"(r[0]), "=r"(r[1]), "=r"(r[2]), "=r"(r[3]) : "r"(addr));
}
__device__ __forceinline__ void mma_bf(float* c, const uint32_t* a, const uint32_t* b){
    asm volatile(
        "mma.sync.aligned.m16n8k16.row.col.f32.bf16.bf16.f32 "
        "{%0,%1,%2,%3}, {%4,%5,%6,%7}, {%8,%9}, {%0,%1,%2,%3};"
        : "+f"(c[0]), "+f"(c[1]), "+f"(c[2]), "+f"(c[3])
        : "r"(a[0]), "r"(a[1]), "r"(a[2]), "r"(a[3]), "r"(b[0]), "r"(b[1]));
}
__device__ __forceinline__ void mma_f16(float* c, const uint32_t* a, const uint32_t* b){
    asm volatile(
        "mma.sync.aligned.m16n8k16.row.col.f32.f16.f16.f32 "
        "{%0,%1,%2,%3}, {%4,%5,%6,%7}, {%8,%9}, {%0,%1,%2,%3};"
        : "+f"(c[0]), "+f"(c[1]), "+f"(c[2]), "+f"(c[3])
        : "r"(a[0]), "r"(a[1]), "r"(a[2]), "r"(a[3]), "r"(b[0]), "r"(b[1]));
}
__device__ __forceinline__ uint32_t cvt_f16x2(float lo, float hi){
    uint32_t r;
    asm("cvt.rn.f16x2.f32 %0, %1, %2;" : "=r"(r) : "f"(hi), "f"(lo));
    return r;
}
__device__ __forceinline__ uint32_t ex2_f16x2(uint32_t x){
    uint32_t r;
    asm("ex2.approx.f16x2 %0, %1;" : "=r"(r) : "r"(x));
    return r;
}
__device__ __forceinline__ float ex2f(float x){
    float r;
    asm("ex2.approx.ftz.f32 %0, %1;" : "=f"(r) : "f"(x));
    return r;
}

// ---------------------------------------------------------------------------
// fp32 -> (bf16 hi, bf16 lo) split
// ---------------------------------------------------------------------------
__global__ void split_kernel(const float* __restrict__ src,
                             __nv_bfloat16* __restrict__ hi,
                             __nv_bfloat16* __restrict__ lo, int n4)
{
    int i = blockIdx.x * blockDim.x + threadIdx.x;
    if (i >= n4) return;
    float4 v = ((const float4*)src)[i];
    __nv_bfloat16 h0 = __float2bfloat16(v.x);
    __nv_bfloat16 h1 = __float2bfloat16(v.y);
    __nv_bfloat16 h2 = __float2bfloat16(v.z);
    __nv_bfloat16 h3 = __float2bfloat16(v.w);
    __nv_bfloat16 l0 = __float2bfloat16(v.x - __bfloat162float(h0));
    __nv_bfloat16 l1 = __float2bfloat16(v.y - __bfloat162float(h1));
    __nv_bfloat16 l2 = __float2bfloat16(v.z - __bfloat162float(h2));
    __nv_bfloat16 l3 = __float2bfloat16(v.w - __bfloat162float(h3));
    ((__nv_bfloat162*)hi)[2*i]   = __halves2bfloat162(h0, h1);
    ((__nv_bfloat162*)hi)[2*i+1] = __halves2bfloat162(h2, h3);
    ((__nv_bfloat162*)lo)[2*i]   = __halves2bfloat162(l0, l1);
    ((__nv_bfloat162*)lo)[2*i+1] = __halves2bfloat162(l2, l3);
}

// ---------------------------------------------------------------------------
// HMMA GEMM, fused 3-pass: per k-chunk stage Ah,Al,Bh,Bl and run
//   acc += Ah@Bh + Al@Bh + Ah@Bl  between ONE pair of syncs.
// Block 128x128, k-chunk 32, 8 warps (2x4), warp tile 64x32.
// Smem: 2 stages x 4 tiles x (128 rows x 80B) = 80KB dynamic.
// ---------------------------------------------------------------------------
#define RB 80
#define OPB (128*RB)            // 10240 bytes per operand tile
#define STB (4*OPB)             // 40960 bytes per stage
#define GEMM_SMEM (2*STB)       // 81920

template<int EPI>
__global__ __launch_bounds__(256, 2)
void hmma_gemm(const __nv_bfloat16* __restrict__ Ah, const __nv_bfloat16* __restrict__ Al,
               const __nv_bfloat16* __restrict__ Bh, const __nv_bfloat16* __restrict__ Bl,
               float* __restrict__ C, int K, int Nfull)
{
    extern __shared__ __align__(16) char smem[];

    const int tid  = threadIdx.x;
    const int lane = tid & 31;
    const int wid  = tid >> 5;
    const int wM   = wid >> 2;
    const int wN   = wid & 3;
    const int bm = blockIdx.y * 128;
    const int bn = blockIdx.x * 128;
    const int NC = K >> 5;

    const uint32_t sb = s2u(smem);

    float acc[4][4][4];
    #pragma unroll
    for (int i = 0; i < 4; i++)
        #pragma unroll
        for (int j = 0; j < 4; j++)
            #pragma unroll
            for (int q = 0; q < 4; q++) acc[i][j][q] = 0.0f;

    uint32_t aoff[4][2], boff[2][2];
    {
        int rA = ((lane >> 3) & 1) * 8 + (lane & 7);
        int cA = (lane >> 4) & 1;
        #pragma unroll
        for (int i = 0; i < 4; i++)
            #pragma unroll
            for (int ks = 0; ks < 2; ks++)
                aoff[i][ks] = (uint32_t)((wM*64 + i*16 + rA) * RB + (ks*2 + cA) * 16);
        int rB = lane & 15;
        int cB = (lane >> 4) & 1;
        #pragma unroll
        for (int j2 = 0; j2 < 2; j2++)
            #pragma unroll
            for (int ks = 0; ks < 2; ks++)
                boff[j2][ks] = (uint32_t)((wN*32 + j2*16 + rB) * RB + (ks*2 + cB) * 16);
    }

    auto prefetch = [&](int c, int buf){
        int kc = c << 5;
        uint32_t st = sb + buf * STB;
        #pragma unroll
        for (int v = 0; v < 2; v++){
            int idx = tid + v * 256;        // 0..511
            int row = idx >> 2;             // 0..127
            int ch  = idx & 3;
            uint32_t so = (uint32_t)(row * RB + ch * 16);
            size_t ga = (size_t)(bm + row) * K + kc + ch * 8;
            size_t gb = (size_t)(bn + row) * K + kc + ch * 8;
            cp16(st + so,           Ah + ga);
            cp16(st + OPB + so,     Al + ga);
            cp16(st + 2*OPB + so,   Bh + gb);
            cp16(st + 3*OPB + so,   Bl + gb);
        }
        asm volatile("cp.async.commit_group;" ::: "memory");
    };

    prefetch(0, 0);
    for (int c = 0; c < NC; c++){
        int buf = c & 1;
        if (c + 1 < NC){
            prefetch(c + 1, buf ^ 1);
            asm volatile("cp.async.wait_group 1;" ::: "memory");
        } else {
            asm volatile("cp.async.wait_group 0;" ::: "memory");
        }
        __syncthreads();

        uint32_t st = sb + buf * STB;
        #pragma unroll
        for (int pass = 0; pass < 3; pass++){
            uint32_t ab = st + (pass == 1 ? OPB : 0);
            uint32_t bb = st + 2*OPB + (pass == 2 ? OPB : 0);
            #pragma unroll
            for (int ks = 0; ks < 2; ks++){
                uint32_t a[4][4];
                #pragma unroll
                for (int i = 0; i < 4; i++) ldmx4(a[i], ab + aoff[i][ks]);
                uint32_t br[2][4];
                #pragma unroll
                for (int j2 = 0; j2 < 2; j2++) ldmx4(br[j2], bb + boff[j2][ks]);
                uint32_t b[4][2];
                #pragma unroll
                for (int j2 = 0; j2 < 2; j2++){
                    b[j2*2+0][0] = br[j2][0]; b[j2*2+0][1] = br[j2][2];
                    b[j2*2+1][0] = br[j2][1]; b[j2*2+1][1] = br[j2][3];
                }
                #pragma unroll
                for (int i = 0; i < 4; i++)
                    #pragma unroll
                    for (int j = 0; j < 4; j++)
                        mma_bf(acc[i][j], a[i], b[j]);
            }
        }
        __syncthreads();
    }

    const int g  = lane >> 2;
    const int tg = lane & 3;
    #pragma unroll
    for (int i = 0; i < 4; i++){
        #pragma unroll
        for (int j = 0; j < 4; j++){
            int col = bn + wN*32 + j*8 + tg*2;
            #pragma unroll
            for (int h2 = 0; h2 < 2; h2++){
                int m = bm + wM*64 + i*16 + g + h2*8;
                float2 val = make_float2(acc[i][j][h2*2], acc[i][j][h2*2+1]);
                if (EPI == 0){
                    *(float2*)(C + (size_t)m * Nfull + col) = val;
                } else {
                    int part = col >> 10;
                    int hh   = (col >> 6) & (Hq - 1);
                    int d0   = col & (Dh - 1);
                    int b    = m >> 11;
                    int t    = m & (Tq - 1);
                    size_t idx = ((size_t)(b*Hq + hh) * Tq + t) * Dh + d0;
                    if (part == 2){
                        __half h0 = __float2half_rn(val.x);
                        __half h1 = __float2half_rn(val.y);
                        __half l0 = __float2half_rn(val.x - __half2float(h0));
                        __half l1 = __float2half_rn(val.y - __half2float(h1));
                        *(__half2*)(g_v_hi + idx) = __halves2half2(h0, h1);
                        *(__half2*)(g_v_lo + idx) = __halves2half2(l0, l1);
                    } else {
                        float* base = (part == 0) ? g_Q : g_K;
                        *(float2*)(base + idx) = val;
                    }
                }
            }
        }
    }
}

// ---------------------------------------------------------------------------
// RoPE: read g_Q/g_K fp32, write bf16 hi/lo (Q scaled by log2e/8)
// ---------------------------------------------------------------------------
#define QSC 0.18033688011112042f   // log2(e)/8

__global__ void rope_kernel(const float* __restrict__ cosT, const float* __restrict__ sinT)
{
    int idx  = blockIdx.x * blockDim.x + threadIdx.x;
    int lane = idx & 31;
    int row  = idx >> 5;
    int t    = row & (Tq - 1);
    size_t base = (size_t)row * Dh;

    float c0 = cosT[t * Dh + lane];
    float c1 = cosT[t * Dh + 32 + lane];
    float s0 = sinT[t * Dh + lane];
    float s1 = sinT[t * Dh + 32 + lane];

    float q0 = g_Q[base + lane], q1 = g_Q[base + 32 + lane];
    float qa = (q0 * c0 - q1 * s0) * QSC;
    float qb = (q1 * c1 + q0 * s1) * QSC;
    __nv_bfloat16 ha = __float2bfloat16(qa);
    __nv_bfloat16 hb = __float2bfloat16(qb);
    g_q_hi[base + lane]      = ha;
    g_q_hi[base + 32 + lane] = hb;
    g_q_lo[base + lane]      = __float2bfloat16(qa - __bfloat162float(ha));
    g_q_lo[base + 32 + lane] = __float2bfloat16(qb - __bfloat162float(hb));

    float k0 = g_K[base + lane], k1 = g_K[base + 32 + lane];
    float ka = k0 * c0 - k1 * s0;
    float kb = k1 * c1 + k0 * s1;
    __nv_bfloat16 hka = __float2bfloat16(ka);
    __nv_bfloat16 hkb = __float2bfloat16(kb);
    g_k_hi[base + lane]      = hka;
    g_k_hi[base + 32 + lane] = hkb;
    g_k_lo[base + lane]      = __float2bfloat16(ka - __bfloat162float(hka));
    g_k_lo[base + 32 + lane] = __float2bfloat16(kb - __bfloat162float(hkb));
}

// ---------------------------------------------------------------------------
// Tensor-core flash attention (causal) — unchanged from round 4 (known-good).
// ---------------------------------------------------------------------------
#define FS_Q 0
#define FS_K 32768
#define FS_V 65536
#define FLASH_SMEM 98304

__global__ __launch_bounds__(256)
void flash_tc()
{
    extern __shared__ __align__(1024) char fsm[];
    const uint32_t sb = s2u(fsm);
    const int tid  = threadIdx.x;
    const int lane = tid & 31;
    const int w    = tid >> 5;
    const int qt   = (int)(gridDim.x - 1 - blockIdx.x);
    const int bh   = blockIdx.y;
    const int b    = bh >> 4, h = bh & (Hq - 1);
    const int nkb  = 2 * qt + 2;

    {
        const __nv_bfloat16* qh = g_q_hi + ((size_t)bh * Tq + (size_t)qt * 128) * Dh;
        const __nv_bfloat16* ql = g_q_lo + ((size_t)bh * Tq + (size_t)qt * 128) * Dh;
        #pragma unroll
        for (int v = 0; v < 4; v++){
            int idx = tid + v * 256;
            int row = idx >> 3;
            int c   = idx & 7;
            uint32_t sw = (uint32_t)(row * 128 + ((c ^ (row & 7)) << 4));
            cp16(sb + FS_Q + sw,         qh + (size_t)row * Dh + c * 8);
            cp16(sb + FS_Q + 16384 + sw, ql + (size_t)row * Dh + c * 8);
        }
    }

    auto prefetch = [&](int kt, int buf){
        size_t off = ((size_t)bh * Tq + (size_t)kt * 64) * Dh;
        const __nv_bfloat16* kh = g_k_hi + off;
        const __nv_bfloat16* kl = g_k_lo + off;
        const __half* vh = g_v_hi + off;
        const __half* vl = g_v_lo + off;
        #pragma unroll
        for (int v = 0; v < 2; v++){
            int idx = tid + v * 256;
            int row = idx >> 3;
            int c   = idx & 7;
            uint32_t sw = (uint32_t)(row * 128 + ((c ^ (row & 7)) << 4));
            cp16(sb + FS_K + buf*16384 + sw,        kh + (size_t)row * Dh + c * 8);
            cp16(sb + FS_K + buf*16384 + 8192 + sw, kl + (size_t)row * Dh + c * 8);
            cp16(sb + FS_V + buf*16384 + sw,        vh + (size_t)row * Dh + c * 8);
            cp16(sb + FS_V + buf*16384 + 8192 + sw, vl + (size_t)row * Dh + c * 8);
        }
        asm volatile("cp.async.commit_group;" ::: "memory");
    };

    prefetch(0, 0);

    float sO[8][4];
    #pragma unroll
    for (int i = 0; i < 8; i++)
        #pragma unroll
        for (int q = 0; q < 4; q++) sO[i][q] = 0.0f;
    float lac[4] = {0.f, 0.f, 0.f, 0.f};
    float m0 = -1e30f, m1 = -1e30f;

    const int rA = ((lane >> 3) & 1) * 8 + (lane & 7);
    const int cA = (lane >> 4) & 1;
    const int rB = lane & 15;
    const int cB = lane >> 4;
    const int qrow = w * 16 + rA;
    const uint32_t ONE2 = 0x3C003C00u;
    const uint32_t ob[2] = {ONE2, ONE2};

    for (int kt = 0; kt < nkb; kt++){
        int buf = kt & 1;
        if (kt + 1 < nkb){
            prefetch(kt + 1, buf ^ 1);
            asm volatile("cp.async.wait_group 1;" ::: "memory");
        } else {
            asm volatile("cp.async.wait_group 0;" ::: "memory");
        }
        __syncthreads();

        bool skip = (kt == 2*qt + 1) && (w < 4);
        if (!skip){
            float s[8][4];
            #pragma unroll
            for (int i = 0; i < 8; i++)
                #pragma unroll
                for (int q = 0; q < 4; q++) s[i][q] = 0.0f;

            #pragma unroll
            for (int pass = 0; pass < 3; pass++){
                uint32_t qb = sb + FS_Q + (pass == 1 ? 16384 : 0);
                uint32_t kbse = sb + FS_K + buf*16384 + (pass == 2 ? 8192 : 0);
                #pragma unroll
                for (int ks = 0; ks < 4; ks++){
                    uint32_t a[4];
                    ldmx4(a, qb + qrow*128 + (((ks*2 + cA) ^ (qrow & 7)) << 4));
                    #pragma unroll
                    for (int j2 = 0; j2 < 4; j2++){
                        int krow = j2*16 + rB;
                        uint32_t br[4];
                        ldmx4(br, kbse + krow*128 + (((ks*2 + cB) ^ (krow & 7)) << 4));
                        uint32_t b0[2] = {br[0], br[2]};
                        uint32_t b1[2] = {br[1], br[3]};
                        mma_bf(s[j2*2],     a, b0);
                        mma_bf(s[j2*2 + 1], a, b1);
                    }
                }
            }

            if (kt >= 2*qt){
                int co = (kt - 2*qt) * 64;
                int lr0 = w*16 + (lane >> 2);
                int lr1 = lr0 + 8;
                #pragma unroll
                for (int nt = 0; nt < 8; nt++){
                    int c0 = co + nt*8 + (lane & 3)*2;
                    if (c0     > lr0) s[nt][0] = -1e30f;
                    if (c0 + 1 > lr0) s[nt][1] = -1e30f;
                    if (c0     > lr1) s[nt][2] = -1e30f;
                    if (c0 + 1 > lr1) s[nt][3] = -1e30f;
                }
            }

            float mx0 = -1e30f, mx1 = -1e30f;
            #pragma unroll
            for (int nt = 0; nt < 8; nt++){
                mx0 = fmaxf(mx0, fmaxf(s[nt][0], s[nt][1]));
                mx1 = fmaxf(mx1, fmaxf(s[nt][2], s[nt][3]));
            }
            mx0 = fmaxf(mx0, __shfl_xor_sync(0xffffffffu, mx0, 1));
            mx0 = fmaxf(mx0, __shfl_xor_sync(0xffffffffu, mx0, 2));
            mx1 = fmaxf(mx1, __shfl_xor_sync(0xffffffffu, mx1, 1));
            mx1 = fmaxf(mx1, __shfl_xor_sync(0xffffffffu, mx1, 2));
            float mn0 = fmaxf(m0, mx0), mn1 = fmaxf(m1, mx1);
            float al0 = ex2f(m0 - mn0), al1 = ex2f(m1 - mn1);
            m0 = mn0; m1 = mn1;
            #pragma unroll
            for (int nt = 0; nt < 8; nt++){
                sO[nt][0] *= al0; sO[nt][1] *= al0;
                sO[nt][2] *= al1; sO[nt][3] *= al1;
            }
            lac[0] *= al0; lac[1] *= al0; lac[2] *= al1; lac[3] *= al1;

            uint32_t P[8][2];
            #pragma unroll
            for (int nt = 0; nt < 8; nt++){
                P[nt][0] = ex2_f16x2(cvt_f16x2(s[nt][0] - mn0, s[nt][1] - mn0));
                P[nt][1] = ex2_f16x2(cvt_f16x2(s[nt][2] - mn1, s[nt][3] - mn1));
            }

            #pragma unroll
            for (int ks = 0; ks < 4; ks++){
                uint32_t a[4] = {P[2*ks][0], P[2*ks][1], P[2*ks+1][0], P[2*ks+1][1]};
                mma_f16(lac, a, ob);
            }

            #pragma unroll
            for (int pass = 0; pass < 2; pass++){
                uint32_t vb = sb + FS_V + buf*16384 + pass*8192;
                #pragma unroll
                for (int ks = 0; ks < 4; ks++){
                    uint32_t a[4] = {P[2*ks][0], P[2*ks][1], P[2*ks+1][0], P[2*ks+1][1]};
                    #pragma unroll
                    for (int dt2 = 0; dt2 < 4; dt2++){
                        int vrow = ks*16 + (lane & 15);
                        int chnk = dt2*2 + (lane >> 4);
                        uint32_t br[4];
                        ldmx4t(br, vb + vrow*128 + ((chnk ^ (vrow & 7)) << 4));
                        uint32_t b0[2] = {br[0], br[1]};
                        uint32_t b1[2] = {br[2], br[3]};
                        mma_f16(sO[dt2*2],     a, b0);
                        mma_f16(sO[dt2*2 + 1], a, b1);
                    }
                }
            }
        }
        __syncthreads();
    }

    float inv0 = 1.0f / lac[0];
    float inv1 = 1.0f / lac[2];
    int tr0 = qt*128 + w*16 + (lane >> 2);
    int tr1 = tr0 + 8;
    #pragma unroll
    for (int dt = 0; dt < 8; dt++){
        int d = dt*8 + (lane & 3)*2;
        float v00 = sO[dt][0] * inv0, v01 = sO[dt][1] * inv0;
        float v10 = sO[dt][2] * inv1, v11 = sO[dt][3] * inv1;
        size_t i0 = ((size_t)(b * Tq + tr0) * Hq + h) * Dh + d;
        size_t i1 = ((size_t)(b * Tq + tr1) * Hq + h) * Dh + d;
        __nv_bfloat16 h00 = __float2bfloat16(v00), h01 = __float2bfloat16(v01);
        __nv_bfloat16 h10 = __float2bfloat16(v10), h11 = __float2bfloat16(v11);
        *(__nv_bfloat162*)(g_o_hi + i0) = __halves2bfloat162(h00, h01);
        *(__nv_bfloat162*)(g_o_hi + i1) = __halves2bfloat162(h10, h11);
        *(__nv_bfloat162*)(g_o_lo + i0) = __halves2bfloat162(
            __float2bfloat16(v00 - __bfloat162float(h00)),
            __float2bfloat16(v01 - __bfloat162float(h01)));
        *(__nv_bfloat162*)(g_o_lo + i1) = __halves2bfloat162(
            __float2bfloat16(v10 - __bfloat162float(h10)),
            __float2bfloat16(v11 - __bfloat162float(h11)));
    }
}

// ---------------------------------------------------------------------------
extern "C" void kernel_launch(void* const* d_in, const int* in_sizes, int n_in,
                              void* d_out, int out_size)
{
    (void)in_sizes; (void)n_in; (void)out_size;
    const float* x     = (const float*)d_in[0];
    const float* cosT  = (const float*)d_in[1];
    const float* sinT  = (const float*)d_in[2];
    const float* w_qkv = (const float*)d_in[3];
    const float* w_out = (const float*)d_in[4];
    float* out = (float*)d_out;

    void *p_xh, *p_xl, *p_wqh, *p_wql, *p_woh, *p_wol, *p_oh, *p_ol;
    cudaGetSymbolAddress(&p_xh,  g_x_hi);  cudaGetSymbolAddress(&p_xl,  g_x_lo);
    cudaGetSymbolAddress(&p_wqh, g_wq_hi); cudaGetSymbolAddress(&p_wql, g_wq_lo);
    cudaGetSymbolAddress(&p_woh, g_wo_hi); cudaGetSymbolAddress(&p_wol, g_wo_lo);
    cudaGetSymbolAddress(&p_oh,  g_o_hi);  cudaGetSymbolAddress(&p_ol,  g_o_lo);

    cudaFuncSetAttribute(flash_tc, cudaFuncAttributeMaxDynamicSharedMemorySize, FLASH_SMEM);
    cudaFuncSetAttribute(hmma_gemm<0>, cudaFuncAttributeMaxDynamicSharedMemorySize, GEMM_SMEM);
    cudaFuncSetAttribute(hmma_gemm<1>, cudaFuncAttributeMaxDynamicSharedMemorySize, GEMM_SMEM);

    // 1) fp32 -> bf16 hi/lo splits of x and weights
    split_kernel<<<(MROWS*Cq/4 + 255)/256, 256>>>(x, (__nv_bfloat16*)p_xh, (__nv_bfloat16*)p_xl, MROWS*Cq/4);
    split_kernel<<<(3*Cq*Cq/4 + 255)/256, 256>>>(w_qkv, (__nv_bfloat16*)p_wqh, (__nv_bfloat16*)p_wql, 3*Cq*Cq/4);
    split_kernel<<<(Cq*Cq/4 + 255)/256, 256>>>(w_out, (__nv_bfloat16*)p_woh, (__nv_bfloat16*)p_wol, Cq*Cq/4);

    // 2) QKV projection: Q,K fp32; V straight to f16 hi/lo
    {
        dim3 grid(3*Cq / 128, MROWS / 128);
        hmma_gemm<1><<<grid, 256, GEMM_SMEM>>>((const __nv_bfloat16*)p_xh, (const __nv_bfloat16*)p_xl,
                                               (const __nv_bfloat16*)p_wqh, (const __nv_bfloat16*)p_wql,
                                               nullptr, Cq, 3*Cq);
    }
    // 3) RoPE -> bf16 hi/lo (Q scaled by log2e/8)
    rope_kernel<<<(Bq*Hq*Tq*32)/256, 256>>>(cosT, sinT);

    // 4) Tensor-core causal flash attention -> g_o_hi/lo
    {
        dim3 grid(Tq / 128, Bq * Hq);
        flash_tc<<<grid, 256, FLASH_SMEM>>>();
    }

    // 5) Output projection
    {
        dim3 grid(Cq / 128, MROWS / 128);
        hmma_gemm<0><<<grid, 256, GEMM_SMEM>>>((const __nv_bfloat16*)p_oh, (const __nv_bfloat16*)p_ol,
                                               (const __nv_bfloat16*)p_woh, (const __nv_bfloat16*)p_wol,
                                               out, Cq, Cq);
    }
}

// round 6
// speedup vs baseline: 5.3112x; 1.8971x over previous
#include <cuda_runtime.h>
#include <cuda_bf16.h>
#include <cuda_fp16.h>
#include <cstdint>

#define Bq 4
#define Tq 2048
#define Cq 1024
#define Hq 16
#define Dh 64
#define MROWS (Bq*Tq)          // 8192
#define NHTD (Bq*Hq*Tq*Dh)     // 8,388,608

// ---------------------------------------------------------------------------
// Device-global scratch
// ---------------------------------------------------------------------------
__device__ float g_Q[NHTD];              // [b,h,t,d] fp32 (pre-rope)
__device__ float g_K[NHTD];              // [b,h,t,d] fp32 (pre-rope)
__device__ __nv_bfloat16 g_q_hi[NHTD], g_q_lo[NHTD];   // post-rope, scaled log2e/8
__device__ __nv_bfloat16 g_k_hi[NHTD], g_k_lo[NHTD];   // post-rope
__device__ __half        g_v_hi[NHTD], g_v_lo[NHTD];   // [b,h,t,d]

__device__ __half g_x16[MROWS*Cq];       // x in f16
__device__ __half g_wq16[3*Cq*Cq];       // w_qkv in f16
__device__ __half g_wo16[Cq*Cq];         // w_out in f16
__device__ __half g_o16[MROWS*Cq];       // attention output [b,t,h,d] f16

// ---------------------------------------------------------------------------
// helpers
// ---------------------------------------------------------------------------
__device__ __forceinline__ uint32_t s2u(const void* p){
    uint32_t a;
    asm("{ .reg .u64 t; cvta.to.shared.u64 t, %1; cvt.u32.u64 %0, t; }" : "=r"(a) : "l"(p));
    return a;
}
__device__ __forceinline__ void cp16(uint32_t dst, const void* src){
    asm volatile("cp.async.cg.shared.global [%0], [%1], 16;" :: "r"(dst), "l"(src));
}
__device__ __forceinline__ void ldmx4(uint32_t* r, uint32_t addr){
    asm volatile("ldmatrix.sync.aligned.m8n8.x4.shared.b16 {%0,%1,%2,%3}, [%4];"
                 : "=r"(r[0]), "=r"(r[1]), "=r"(r[2]), "=r"(r[3]) : "r"(addr));
}
__device__ __forceinline__ void ldmx4t(uint32_t* r, uint32_t addr){
    asm volatile("ldmatrix.sync.aligned.m8n8.x4.trans.shared.b16 {%0,%1,%2,%3}, [%4];"
                 : "=r"(r[0]), "=r"(r[1]), "=r"(r[2]), "=r"(r[3]) : "r"(addr));
}
__device__ __forceinline__ void mma_bf(float* c, const uint32_t* a, const uint32_t* b){
    asm volatile(
        "mma.sync.aligned.m16n8k16.row.col.f32.bf16.bf16.f32 "
        "{%0,%1,%2,%3}, {%4,%5,%6,%7}, {%8,%9}, {%0,%1,%2,%3};"
        : "+f"(c[0]), "+f"(c[1]), "+f"(c[2]), "+f"(c[3])
        : "r"(a[0]), "r"(a[1]), "r"(a[2]), "r"(a[3]), "r"(b[0]), "r"(b[1]));
}
__device__ __forceinline__ void mma_f16(float* c, const uint32_t* a, const uint32_t* b){
    asm volatile(
        "mma.sync.aligned.m16n8k16.row.col.f32.f16.f16.f32 "
        "{%0,%1,%2,%3}, {%4,%5,%6,%7}, {%8,%9}, {%0,%1,%2,%3};"
        : "+f"(c[0]), "+f"(c[1]), "+f"(c[2]), "+f"(c[3])
        : "r"(a[0]), "r"(a[1]), "r"(a[2]), "r"(a[3]), "r"(b[0]), "r"(b[1]));
}
__device__ __forceinline__ uint32_t cvt_f16x2(float lo, float hi){
    uint32_t r;
    asm("cvt.rn.f16x2.f32 %0, %1, %2;" : "=r"(r) : "f"(hi), "f"(lo));
    return r;
}
__device__ __forceinline__ uint32_t ex2_f16x2(uint32_t x){
    uint32_t r;
    asm("ex2.approx.f16x2 %0, %1;" : "=r"(r) : "r"(x));
    return r;
}
__device__ __forceinline__ float ex2f(float x){
    float r;
    asm("ex2.approx.ftz.f32 %0, %1;" : "=f"(r) : "f"(x));
    return r;
}

// ---------------------------------------------------------------------------
// fp32 -> fp16 convert
// ---------------------------------------------------------------------------
__global__ void cvt16_kernel(const float* __restrict__ src,
                             __half* __restrict__ dst, int n4)
{
    int i = blockIdx.x * blockDim.x + threadIdx.x;
    if (i >= n4) return;
    float4 v = ((const float4*)src)[i];
    ((__half2*)dst)[2*i]   = __halves2half2(__float2half_rn(v.x), __float2half_rn(v.y));
    ((__half2*)dst)[2*i+1] = __halves2half2(__float2half_rn(v.z), __float2half_rn(v.w));
}

// ---------------------------------------------------------------------------
// Single-pass f16 HMMA GEMM: C[M,N] = A[M,K] @ B[N,K]^T  (fp32 accum)
// Block 128x128, K-chunk 64, 8 warps (2x4), warp tile 64x32.
// 3-stage cp.async pipeline; 128B rows + XOR swizzle (conflict-free ldmatrix).
// EPI=0: C[m,Nfull] fp32.  EPI=1: Q/K fp32 scatter, V f16 hi/lo ([b,h,t,d]).
// ---------------------------------------------------------------------------
#define ROWB 128
#define OPB (128*ROWB)          // 16384 bytes per operand tile
#define STB (2*OPB)             // 32768 per stage (A+B)
#define GEMM_SMEM (3*STB)       // 98304

template<int EPI>
__global__ __launch_bounds__(256, 2)
void h16_gemm(const __half* __restrict__ A, const __half* __restrict__ B,
              float* __restrict__ C, int K, int Nfull)
{
    extern __shared__ __align__(16) char smem[];
    const uint32_t sb = s2u(smem);

    const int tid  = threadIdx.x;
    const int lane = tid & 31;
    const int wid  = tid >> 5;
    const int wM   = wid >> 2;
    const int wN   = wid & 3;
    const int bm = blockIdx.y * 128;
    const int bn = blockIdx.x * 128;
    const int NC = K >> 6;          // 64-wide k-chunks

    float acc[4][4][4];
    #pragma unroll
    for (int i = 0; i < 4; i++)
        #pragma unroll
        for (int j = 0; j < 4; j++)
            #pragma unroll
            for (int q = 0; q < 4; q++) acc[i][j][q] = 0.0f;

    const int rA = ((lane >> 3) & 1) * 8 + (lane & 7);
    const int cA = (lane >> 4) & 1;
    const int rB = lane & 15;
    const int cB = lane >> 4;

    auto prefetch = [&](int c, int st){
        uint32_t base = sb + st * STB;
        int kc = c << 6;
        #pragma unroll
        for (int v = 0; v < 4; v++){
            int idx = tid + v * 256;        // 0..1023
            int row = idx >> 3;             // 0..127
            int ch  = idx & 7;
            uint32_t sw = (uint32_t)(row * ROWB + ((ch ^ (row & 7)) << 4));
            cp16(base + sw,       A + (size_t)(bm + row) * K + kc + ch * 8);
            cp16(base + OPB + sw, B + (size_t)(bn + row) * K + kc + ch * 8);
        }
        asm volatile("cp.async.commit_group;" ::: "memory");
    };

    prefetch(0, 0);
    prefetch(1, 1);
    for (int c = 0; c < NC; c++){
        int st = c % 3;
        if (c + 2 < NC){
            prefetch(c + 2, (c + 2) % 3);
            asm volatile("cp.async.wait_group 2;" ::: "memory");
        } else if (c + 1 < NC){
            asm volatile("cp.async.wait_group 1;" ::: "memory");
        } else {
            asm volatile("cp.async.wait_group 0;" ::: "memory");
        }
        __syncthreads();

        uint32_t ab = sb + st * STB;
        uint32_t bb = ab + OPB;
        #pragma unroll
        for (int ks = 0; ks < 4; ks++){
            uint32_t a[4][4];
            #pragma unroll
            for (int i = 0; i < 4; i++){
                int arow = wM*64 + i*16 + rA;
                ldmx4(a[i], ab + arow*ROWB + (((ks*2 + cA) ^ (arow & 7)) << 4));
            }
            uint32_t br[2][4];
            #pragma unroll
            for (int j2 = 0; j2 < 2; j2++){
                int brow = wN*32 + j2*16 + rB;
                ldmx4(br[j2], bb + brow*ROWB + (((ks*2 + cB) ^ (brow & 7)) << 4));
            }
            uint32_t b[4][2];
            #pragma unroll
            for (int j2 = 0; j2 < 2; j2++){
                b[j2*2+0][0] = br[j2][0]; b[j2*2+0][1] = br[j2][2];
                b[j2*2+1][0] = br[j2][1]; b[j2*2+1][1] = br[j2][3];
            }
            #pragma unroll
            for (int i = 0; i < 4; i++)
                #pragma unroll
                for (int j = 0; j < 4; j++)
                    mma_f16(acc[i][j], a[i], b[j]);
        }
        __syncthreads();
    }

    const int g  = lane >> 2;
    const int tg = lane & 3;
    #pragma unroll
    for (int i = 0; i < 4; i++){
        #pragma unroll
        for (int j = 0; j < 4; j++){
            int col = bn + wN*32 + j*8 + tg*2;
            #pragma unroll
            for (int h2 = 0; h2 < 2; h2++){
                int m = bm + wM*64 + i*16 + g + h2*8;
                float2 val = make_float2(acc[i][j][h2*2], acc[i][j][h2*2+1]);
                if (EPI == 0){
                    *(float2*)(C + (size_t)m * Nfull + col) = val;
                } else {
                    int part = col >> 10;
                    int hh   = (col >> 6) & (Hq - 1);
                    int d0   = col & (Dh - 1);
                    int b    = m >> 11;
                    int t    = m & (Tq - 1);
                    size_t idx = ((size_t)(b*Hq + hh) * Tq + t) * Dh + d0;
                    if (part == 2){
                        __half h0 = __float2half_rn(val.x);
                        __half h1 = __float2half_rn(val.y);
                        __half l0 = __float2half_rn(val.x - __half2float(h0));
                        __half l1 = __float2half_rn(val.y - __half2float(h1));
                        *(__half2*)(g_v_hi + idx) = __halves2half2(h0, h1);
                        *(__half2*)(g_v_lo + idx) = __halves2half2(l0, l1);
                    } else {
                        float* base = (part == 0) ? g_Q : g_K;
                        *(float2*)(base + idx) = val;
                    }
                }
            }
        }
    }
}

// ---------------------------------------------------------------------------
// RoPE: read g_Q/g_K fp32, write bf16 hi/lo (Q scaled by log2e/8)
// ---------------------------------------------------------------------------
#define QSC 0.18033688011112042f   // log2(e)/8

__global__ void rope_kernel(const float* __restrict__ cosT, const float* __restrict__ sinT)
{
    int idx  = blockIdx.x * blockDim.x + threadIdx.x;
    int lane = idx & 31;
    int row  = idx >> 5;
    int t    = row & (Tq - 1);
    size_t base = (size_t)row * Dh;

    float c0 = cosT[t * Dh + lane];
    float c1 = cosT[t * Dh + 32 + lane];
    float s0 = sinT[t * Dh + lane];
    float s1 = sinT[t * Dh + 32 + lane];

    float q0 = g_Q[base + lane], q1 = g_Q[base + 32 + lane];
    float qa = (q0 * c0 - q1 * s0) * QSC;
    float qb = (q1 * c1 + q0 * s1) * QSC;
    __nv_bfloat16 ha = __float2bfloat16(qa);
    __nv_bfloat16 hb = __float2bfloat16(qb);
    g_q_hi[base + lane]      = ha;
    g_q_hi[base + 32 + lane] = hb;
    g_q_lo[base + lane]      = __float2bfloat16(qa - __bfloat162float(ha));
    g_q_lo[base + 32 + lane] = __float2bfloat16(qb - __bfloat162float(hb));

    float k0 = g_K[base + lane], k1 = g_K[base + 32 + lane];
    float ka = k0 * c0 - k1 * s0;
    float kb = k1 * c1 + k0 * s1;
    __nv_bfloat16 hka = __float2bfloat16(ka);
    __nv_bfloat16 hkb = __float2bfloat16(kb);
    g_k_hi[base + lane]      = hka;
    g_k_hi[base + 32 + lane] = hkb;
    g_k_lo[base + lane]      = __float2bfloat16(ka - __bfloat162float(hka));
    g_k_lo[base + 32 + lane] = __float2bfloat16(kb - __bfloat162float(hkb));
}

// ---------------------------------------------------------------------------
// Tensor-core flash attention (causal). Epilogue now writes f16 O.
// ---------------------------------------------------------------------------
#define FS_Q 0
#define FS_K 32768
#define FS_V 65536
#define FLASH_SMEM 98304

__global__ __launch_bounds__(256)
void flash_tc()
{
    extern __shared__ __align__(1024) char fsm[];
    const uint32_t sb = s2u(fsm);
    const int tid  = threadIdx.x;
    const int lane = tid & 31;
    const int w    = tid >> 5;
    const int qt   = (int)(gridDim.x - 1 - blockIdx.x);
    const int bh   = blockIdx.y;
    const int b    = bh >> 4, h = bh & (Hq - 1);
    const int nkb  = 2 * qt + 2;

    {
        const __nv_bfloat16* qh = g_q_hi + ((size_t)bh * Tq + (size_t)qt * 128) * Dh;
        const __nv_bfloat16* ql = g_q_lo + ((size_t)bh * Tq + (size_t)qt * 128) * Dh;
        #pragma unroll
        for (int v = 0; v < 4; v++){
            int idx = tid + v * 256;
            int row = idx >> 3;
            int c   = idx & 7;
            uint32_t sw = (uint32_t)(row * 128 + ((c ^ (row & 7)) << 4));
            cp16(sb + FS_Q + sw,         qh + (size_t)row * Dh + c * 8);
            cp16(sb + FS_Q + 16384 + sw, ql + (size_t)row * Dh + c * 8);
        }
    }

    auto prefetch = [&](int kt, int buf){
        size_t off = ((size_t)bh * Tq + (size_t)kt * 64) * Dh;
        const __nv_bfloat16* kh = g_k_hi + off;
        const __nv_bfloat16* kl = g_k_lo + off;
        const __half* vh = g_v_hi + off;
        const __half* vl = g_v_lo + off;
        #pragma unroll
        for (int v = 0; v < 2; v++){
            int idx = tid + v * 256;
            int row = idx >> 3;
            int c   = idx & 7;
            uint32_t sw = (uint32_t)(row * 128 + ((c ^ (row & 7)) << 4));
            cp16(sb + FS_K + buf*16384 + sw,        kh + (size_t)row * Dh + c * 8);
            cp16(sb + FS_K + buf*16384 + 8192 + sw, kl + (size_t)row * Dh + c * 8);
            cp16(sb + FS_V + buf*16384 + sw,        vh + (size_t)row * Dh + c * 8);
            cp16(sb + FS_V + buf*16384 + 8192 + sw, vl + (size_t)row * Dh + c * 8);
        }
        asm volatile("cp.async.commit_group;" ::: "memory");
    };

    prefetch(0, 0);

    float sO[8][4];
    #pragma unroll
    for (int i = 0; i < 8; i++)
        #pragma unroll
        for (int q = 0; q < 4; q++) sO[i][q] = 0.0f;
    float lac[4] = {0.f, 0.f, 0.f, 0.f};
    float m0 = -1e30f, m1 = -1e30f;

    const int rA = ((lane >> 3) & 1) * 8 + (lane & 7);
    const int cA = (lane >> 4) & 1;
    const int rB = lane & 15;
    const int cB = lane >> 4;
    const int qrow = w * 16 + rA;
    const uint32_t ONE2 = 0x3C003C00u;
    const uint32_t ob[2] = {ONE2, ONE2};

    for (int kt = 0; kt < nkb; kt++){
        int buf = kt & 1;
        if (kt + 1 < nkb){
            prefetch(kt + 1, buf ^ 1);
            asm volatile("cp.async.wait_group 1;" ::: "memory");
        } else {
            asm volatile("cp.async.wait_group 0;" ::: "memory");
        }
        __syncthreads();

        bool skip = (kt == 2*qt + 1) && (w < 4);
        if (!skip){
            float s[8][4];
            #pragma unroll
            for (int i = 0; i < 8; i++)
                #pragma unroll
                for (int q = 0; q < 4; q++) s[i][q] = 0.0f;

            #pragma unroll
            for (int pass = 0; pass < 3; pass++){
                uint32_t qb = sb + FS_Q + (pass == 1 ? 16384 : 0);
                uint32_t kbse = sb + FS_K + buf*16384 + (pass == 2 ? 8192 : 0);
                #pragma unroll
                for (int ks = 0; ks < 4; ks++){
                    uint32_t a[4];
                    ldmx4(a, qb + qrow*128 + (((ks*2 + cA) ^ (qrow & 7)) << 4));
                    #pragma unroll
                    for (int j2 = 0; j2 < 4; j2++){
                        int krow = j2*16 + rB;
                        uint32_t br[4];
                        ldmx4(br, kbse + krow*128 + (((ks*2 + cB) ^ (krow & 7)) << 4));
                        uint32_t b0[2] = {br[0], br[2]};
                        uint32_t b1[2] = {br[1], br[3]};
                        mma_bf(s[j2*2],     a, b0);
                        mma_bf(s[j2*2 + 1], a, b1);
                    }
                }
            }

            if (kt >= 2*qt){
                int co = (kt - 2*qt) * 64;
                int lr0 = w*16 + (lane >> 2);
                int lr1 = lr0 + 8;
                #pragma unroll
                for (int nt = 0; nt < 8; nt++){
                    int c0 = co + nt*8 + (lane & 3)*2;
                    if (c0     > lr0) s[nt][0] = -1e30f;
                    if (c0 + 1 > lr0) s[nt][1] = -1e30f;
                    if (c0     > lr1) s[nt][2] = -1e30f;
                    if (c0 + 1 > lr1) s[nt][3] = -1e30f;
                }
            }

            float mx0 = -1e30f, mx1 = -1e30f;
            #pragma unroll
            for (int nt = 0; nt < 8; nt++){
                mx0 = fmaxf(mx0, fmaxf(s[nt][0], s[nt][1]));
                mx1 = fmaxf(mx1, fmaxf(s[nt][2], s[nt][3]));
            }
            mx0 = fmaxf(mx0, __shfl_xor_sync(0xffffffffu, mx0, 1));
            mx0 = fmaxf(mx0, __shfl_xor_sync(0xffffffffu, mx0, 2));
            mx1 = fmaxf(mx1, __shfl_xor_sync(0xffffffffu, mx1, 1));
            mx1 = fmaxf(mx1, __shfl_xor_sync(0xffffffffu, mx1, 2));
            float mn0 = fmaxf(m0, mx0), mn1 = fmaxf(m1, mx1);
            float al0 = ex2f(m0 - mn0), al1 = ex2f(m1 - mn1);
            m0 = mn0; m1 = mn1;
            #pragma unroll
            for (int nt = 0; nt < 8; nt++){
                sO[nt][0] *= al0; sO[nt][1] *= al0;
                sO[nt][2] *= al1; sO[nt][3] *= al1;
            }
            lac[0] *= al0; lac[1] *= al0; lac[2] *= al1; lac[3] *= al1;

            uint32_t P[8][2];
            #pragma unroll
            for (int nt = 0; nt < 8; nt++){
                P[nt][0] = ex2_f16x2(cvt_f16x2(s[nt][0] - mn0, s[nt][1] - mn0));
                P[nt][1] = ex2_f16x2(cvt_f16x2(s[nt][2] - mn1, s[nt][3] - mn1));
            }

            #pragma unroll
            for (int ks = 0; ks < 4; ks++){
                uint32_t a[4] = {P[2*ks][0], P[2*ks][1], P[2*ks+1][0], P[2*ks+1][1]};
                mma_f16(lac, a, ob);
            }

            #pragma unroll
            for (int pass = 0; pass < 2; pass++){
                uint32_t vb = sb + FS_V + buf*16384 + pass*8192;
                #pragma unroll
                for (int ks = 0; ks < 4; ks++){
                    uint32_t a[4] = {P[2*ks][0], P[2*ks][1], P[2*ks+1][0], P[2*ks+1][1]};
                    #pragma unroll
                    for (int dt2 = 0; dt2 < 4; dt2++){
                        int vrow = ks*16 + (lane & 15);
                        int chnk = dt2*2 + (lane >> 4);
                        uint32_t br[4];
                        ldmx4t(br, vb + vrow*128 + ((chnk ^ (vrow & 7)) << 4));
                        uint32_t b0[2] = {br[0], br[1]};
                        uint32_t b1[2] = {br[2], br[3]};
                        mma_f16(sO[dt2*2],     a, b0);
                        mma_f16(sO[dt2*2 + 1], a, b1);
                    }
                }
            }
        }
        __syncthreads();
    }

    float inv0 = 1.0f / lac[0];
    float inv1 = 1.0f / lac[2];
    int tr0 = qt*128 + w*16 + (lane >> 2);
    int tr1 = tr0 + 8;
    #pragma unroll
    for (int dt = 0; dt < 8; dt++){
        int d = dt*8 + (lane & 3)*2;
        size_t i0 = ((size_t)(b * Tq + tr0) * Hq + h) * Dh + d;
        size_t i1 = ((size_t)(b * Tq + tr1) * Hq + h) * Dh + d;
        *(__half2*)(g_o16 + i0) = __halves2half2(
            __float2half_rn(sO[dt][0] * inv0), __float2half_rn(sO[dt][1] * inv0));
        *(__half2*)(g_o16 + i1) = __halves2half2(
            __float2half_rn(sO[dt][2] * inv1), __float2half_rn(sO[dt][3] * inv1));
    }
}

// ---------------------------------------------------------------------------
extern "C" void kernel_launch(void* const* d_in, const int* in_sizes, int n_in,
                              void* d_out, int out_size)
{
    (void)in_sizes; (void)n_in; (void)out_size;
    const float* x     = (const float*)d_in[0];
    const float* cosT  = (const float*)d_in[1];
    const float* sinT  = (const float*)d_in[2];
    const float* w_qkv = (const float*)d_in[3];
    const float* w_out = (const float*)d_in[4];
    float* out = (float*)d_out;

    void *p_x16, *p_wq16, *p_wo16, *p_o16;
    cudaGetSymbolAddress(&p_x16,  g_x16);
    cudaGetSymbolAddress(&p_wq16, g_wq16);
    cudaGetSymbolAddress(&p_wo16, g_wo16);
    cudaGetSymbolAddress(&p_o16,  g_o16);

    cudaFuncSetAttribute(flash_tc, cudaFuncAttributeMaxDynamicSharedMemorySize, FLASH_SMEM);
    cudaFuncSetAttribute(h16_gemm<0>, cudaFuncAttributeMaxDynamicSharedMemorySize, GEMM_SMEM);
    cudaFuncSetAttribute(h16_gemm<1>, cudaFuncAttributeMaxDynamicSharedMemorySize, GEMM_SMEM);

    // 1) fp32 -> fp16 converts
    cvt16_kernel<<<(MROWS*Cq/4 + 255)/256, 256>>>(x, (__half*)p_x16, MROWS*Cq/4);
    cvt16_kernel<<<(3*Cq*Cq/4 + 255)/256, 256>>>(w_qkv, (__half*)p_wq16, 3*Cq*Cq/4);
    cvt16_kernel<<<(Cq*Cq/4 + 255)/256, 256>>>(w_out, (__half*)p_wo16, Cq*Cq/4);

    // 2) QKV projection (single-pass f16 HMMA): Q,K fp32; V f16 hi/lo
    {
        dim3 grid(3*Cq / 128, MROWS / 128);   // (24, 64)
        h16_gemm<1><<<grid, 256, GEMM_SMEM>>>((const __half*)p_x16, (const __half*)p_wq16,
                                              nullptr, Cq, 3*Cq);
    }
    // 3) RoPE -> bf16 hi/lo (Q scaled by log2e/8)
    rope_kernel<<<(Bq*Hq*Tq*32)/256, 256>>>(cosT, sinT);

    // 4) Tensor-core causal flash attention -> g_o16 (f16)
    {
        dim3 grid(Tq / 128, Bq * Hq);
        flash_tc<<<grid, 256, FLASH_SMEM>>>();
    }

    // 5) Output projection (single-pass f16 HMMA)
    {
        dim3 grid(Cq / 128, MROWS / 128);     // (8, 64)
        h16_gemm<0><<<grid, 256, GEMM_SMEM>>>((const __half*)p_o16, (const __half*)p_wo16,
                                              out, Cq, Cq);
    }
}

// round 7
// speedup vs baseline: 7.4435x; 1.4015x over previous
#include <cuda_runtime.h>
#include <cuda_bf16.h>
#include <cuda_fp16.h>
#include <cstdint>

#define Bq 4
#define Tq 2048
#define Cq 1024
#define Hq 16
#define Dh 64
#define MROWS (Bq*Tq)          // 8192
#define NHTD (Bq*Hq*Tq*Dh)     // 8,388,608

// ---------------------------------------------------------------------------
// Device-global scratch
// ---------------------------------------------------------------------------
__device__ float g_Q[NHTD];              // [b,h,t,d] fp32 (pre-rope)
__device__ float g_K[NHTD];              // [b,h,t,d] fp32 (pre-rope)
__device__ __half g_q16[NHTD];           // post-rope, scaled log2e/8, f16
__device__ __half g_k16[NHTD];           // post-rope, f16
__device__ __half g_v16[NHTD];           // [b,h,t,d] f16

__device__ __half g_x16[MROWS*Cq];       // x in f16
__device__ __half g_wq16[3*Cq*Cq];       // w_qkv in f16
__device__ __half g_wo16[Cq*Cq];         // w_out in f16
__device__ __half g_o16[MROWS*Cq];       // attention output [b,t,h,d] f16

// ---------------------------------------------------------------------------
// helpers
// ---------------------------------------------------------------------------
__device__ __forceinline__ uint32_t s2u(const void* p){
    uint32_t a;
    asm("{ .reg .u64 t; cvta.to.shared.u64 t, %1; cvt.u32.u64 %0, t; }" : "=r"(a) : "l"(p));
    return a;
}
__device__ __forceinline__ void cp16(uint32_t dst, const void* src){
    asm volatile("cp.async.cg.shared.global [%0], [%1], 16;" :: "r"(dst), "l"(src));
}
__device__ __forceinline__ void ldmx4(uint32_t* r, uint32_t addr){
    asm volatile("ldmatrix.sync.aligned.m8n8.x4.shared.b16 {%0,%1,%2,%3}, [%4];"
                 : "=r"(r[0]), "=r"(r[1]), "=r"(r[2]), "=r"(r[3]) : "r"(addr));
}
__device__ __forceinline__ void ldmx4t(uint32_t* r, uint32_t addr){
    asm volatile("ldmatrix.sync.aligned.m8n8.x4.trans.shared.b16 {%0,%1,%2,%3}, [%4];"
                 : "=r"(r[0]), "=r"(r[1]), "=r"(r[2]), "=r"(r[3]) : "r"(addr));
}
__device__ __forceinline__ void mma_f16(float* c, const uint32_t* a, const uint32_t* b){
    asm volatile(
        "mma.sync.aligned.m16n8k16.row.col.f32.f16.f16.f32 "
        "{%0,%1,%2,%3}, {%4,%5,%6,%7}, {%8,%9}, {%0,%1,%2,%3};"
        : "+f"(c[0]), "+f"(c[1]), "+f"(c[2]), "+f"(c[3])
        : "r"(a[0]), "r"(a[1]), "r"(a[2]), "r"(a[3]), "r"(b[0]), "r"(b[1]));
}
__device__ __forceinline__ uint32_t cvt_f16x2(float lo, float hi){
    uint32_t r;
    asm("cvt.rn.f16x2.f32 %0, %1, %2;" : "=r"(r) : "f"(hi), "f"(lo));
    return r;
}
__device__ __forceinline__ uint32_t ex2_f16x2(uint32_t x){
    uint32_t r;
    asm("ex2.approx.f16x2 %0, %1;" : "=r"(r) : "r"(x));
    return r;
}
__device__ __forceinline__ float ex2f(float x){
    float r;
    asm("ex2.approx.ftz.f32 %0, %1;" : "=f"(r) : "f"(x));
    return r;
}

// ---------------------------------------------------------------------------
// fp32 -> fp16 convert
// ---------------------------------------------------------------------------
__global__ void cvt16_kernel(const float* __restrict__ src,
                             __half* __restrict__ dst, int n4)
{
    int i = blockIdx.x * blockDim.x + threadIdx.x;
    if (i >= n4) return;
    float4 v = ((const float4*)src)[i];
    ((__half2*)dst)[2*i]   = __halves2half2(__float2half_rn(v.x), __float2half_rn(v.y));
    ((__half2*)dst)[2*i+1] = __halves2half2(__float2half_rn(v.z), __float2half_rn(v.w));
}

// ---------------------------------------------------------------------------
// Single-pass f16 HMMA GEMM (unchanged from round 6, except V epilogue
// writes a single f16 copy).
// ---------------------------------------------------------------------------
#define ROWB 128
#define OPB (128*ROWB)          // 16384 bytes per operand tile
#define STB (2*OPB)             // 32768 per stage (A+B)
#define GEMM_SMEM (3*STB)       // 98304

template<int EPI>
__global__ __launch_bounds__(256, 2)
void h16_gemm(const __half* __restrict__ A, const __half* __restrict__ B,
              float* __restrict__ C, int K, int Nfull)
{
    extern __shared__ __align__(16) char smem[];
    const uint32_t sb = s2u(smem);

    const int tid  = threadIdx.x;
    const int lane = tid & 31;
    const int wid  = tid >> 5;
    const int wM   = wid >> 2;
    const int wN   = wid & 3;
    const int bm = blockIdx.y * 128;
    const int bn = blockIdx.x * 128;
    const int NC = K >> 6;          // 64-wide k-chunks

    float acc[4][4][4];
    #pragma unroll
    for (int i = 0; i < 4; i++)
        #pragma unroll
        for (int j = 0; j < 4; j++)
            #pragma unroll
            for (int q = 0; q < 4; q++) acc[i][j][q] = 0.0f;

    const int rA = ((lane >> 3) & 1) * 8 + (lane & 7);
    const int cA = (lane >> 4) & 1;
    const int rB = lane & 15;
    const int cB = lane >> 4;

    auto prefetch = [&](int c, int st){
        uint32_t base = sb + st * STB;
        int kc = c << 6;
        #pragma unroll
        for (int v = 0; v < 4; v++){
            int idx = tid + v * 256;        // 0..1023
            int row = idx >> 3;             // 0..127
            int ch  = idx & 7;
            uint32_t sw = (uint32_t)(row * ROWB + ((ch ^ (row & 7)) << 4));
            cp16(base + sw,       A + (size_t)(bm + row) * K + kc + ch * 8);
            cp16(base + OPB + sw, B + (size_t)(bn + row) * K + kc + ch * 8);
        }
        asm volatile("cp.async.commit_group;" ::: "memory");
    };

    prefetch(0, 0);
    prefetch(1, 1);
    for (int c = 0; c < NC; c++){
        int st = c % 3;
        if (c + 2 < NC){
            prefetch(c + 2, (c + 2) % 3);
            asm volatile("cp.async.wait_group 2;" ::: "memory");
        } else if (c + 1 < NC){
            asm volatile("cp.async.wait_group 1;" ::: "memory");
        } else {
            asm volatile("cp.async.wait_group 0;" ::: "memory");
        }
        __syncthreads();

        uint32_t ab = sb + st * STB;
        uint32_t bb = ab + OPB;
        #pragma unroll
        for (int ks = 0; ks < 4; ks++){
            uint32_t a[4][4];
            #pragma unroll
            for (int i = 0; i < 4; i++){
                int arow = wM*64 + i*16 + rA;
                ldmx4(a[i], ab + arow*ROWB + (((ks*2 + cA) ^ (arow & 7)) << 4));
            }
            uint32_t br[2][4];
            #pragma unroll
            for (int j2 = 0; j2 < 2; j2++){
                int brow = wN*32 + j2*16 + rB;
                ldmx4(br[j2], bb + brow*ROWB + (((ks*2 + cB) ^ (brow & 7)) << 4));
            }
            uint32_t b[4][2];
            #pragma unroll
            for (int j2 = 0; j2 < 2; j2++){
                b[j2*2+0][0] = br[j2][0]; b[j2*2+0][1] = br[j2][2];
                b[j2*2+1][0] = br[j2][1]; b[j2*2+1][1] = br[j2][3];
            }
            #pragma unroll
            for (int i = 0; i < 4; i++)
                #pragma unroll
                for (int j = 0; j < 4; j++)
                    mma_f16(acc[i][j], a[i], b[j]);
        }
        __syncthreads();
    }

    const int g  = lane >> 2;
    const int tg = lane & 3;
    #pragma unroll
    for (int i = 0; i < 4; i++){
        #pragma unroll
        for (int j = 0; j < 4; j++){
            int col = bn + wN*32 + j*8 + tg*2;
            #pragma unroll
            for (int h2 = 0; h2 < 2; h2++){
                int m = bm + wM*64 + i*16 + g + h2*8;
                float2 val = make_float2(acc[i][j][h2*2], acc[i][j][h2*2+1]);
                if (EPI == 0){
                    *(float2*)(C + (size_t)m * Nfull + col) = val;
                } else {
                    int part = col >> 10;
                    int hh   = (col >> 6) & (Hq - 1);
                    int d0   = col & (Dh - 1);
                    int b    = m >> 11;
                    int t    = m & (Tq - 1);
                    size_t idx = ((size_t)(b*Hq + hh) * Tq + t) * Dh + d0;
                    if (part == 2){
                        *(__half2*)(g_v16 + idx) = __halves2half2(
                            __float2half_rn(val.x), __float2half_rn(val.y));
                    } else {
                        float* base = (part == 0) ? g_Q : g_K;
                        *(float2*)(base + idx) = val;
                    }
                }
            }
        }
    }
}

// ---------------------------------------------------------------------------
// RoPE: read g_Q/g_K fp32, write f16 (Q scaled by log2e/8)
// ---------------------------------------------------------------------------
#define QSC 0.18033688011112042f   // log2(e)/8

__global__ void rope_kernel(const float* __restrict__ cosT, const float* __restrict__ sinT)
{
    int idx  = blockIdx.x * blockDim.x + threadIdx.x;
    int lane = idx & 31;
    int row  = idx >> 5;
    int t    = row & (Tq - 1);
    size_t base = (size_t)row * Dh;

    float c0 = cosT[t * Dh + lane];
    float c1 = cosT[t * Dh + 32 + lane];
    float s0 = sinT[t * Dh + lane];
    float s1 = sinT[t * Dh + 32 + lane];

    float q0 = g_Q[base + lane], q1 = g_Q[base + 32 + lane];
    g_q16[base + lane]      = __float2half_rn((q0 * c0 - q1 * s0) * QSC);
    g_q16[base + 32 + lane] = __float2half_rn((q1 * c1 + q0 * s1) * QSC);

    float k0 = g_K[base + lane], k1 = g_K[base + 32 + lane];
    g_k16[base + lane]      = __float2half_rn(k0 * c0 - k1 * s0);
    g_k16[base + 32 + lane] = __float2half_rn(k1 * c1 + k0 * s1);
}

// ---------------------------------------------------------------------------
// Tensor-core flash attention (causal), all-f16 single-pass.
// CTA = 128 q-rows, 8 warps x 16 rows. k-blocks of 64, double-buffered.
// Smem: Q 16KB + K 2x8KB + V 2x8KB = 48KB -> 2 CTAs/SM.
// ---------------------------------------------------------------------------
#define FS_Q 0            // 128 x 128B
#define FS_K 16384        // buf b: +b*8192
#define FS_V 32768        // buf b: +b*8192
#define FLASH_SMEM 49152

__global__ __launch_bounds__(256)
void flash_tc()
{
    extern __shared__ __align__(1024) char fsm[];
    const uint32_t sb = s2u(fsm);
    const int tid  = threadIdx.x;
    const int lane = tid & 31;
    const int w    = tid >> 5;
    const int qt   = (int)(gridDim.x - 1 - blockIdx.x);
    const int bh   = blockIdx.y;
    const int b    = bh >> 4, h = bh & (Hq - 1);
    const int nkb  = 2 * qt + 2;

    // ---- load Q tile (f16), swizzled 128B rows ----
    {
        const __half* q16 = g_q16 + ((size_t)bh * Tq + (size_t)qt * 128) * Dh;
        #pragma unroll
        for (int v = 0; v < 4; v++){
            int idx = tid + v * 256;          // 0..1023
            int row = idx >> 3;               // 0..127
            int c   = idx & 7;
            uint32_t sw = (uint32_t)(row * 128 + ((c ^ (row & 7)) << 4));
            cp16(sb + FS_Q + sw, q16 + (size_t)row * Dh + c * 8);
        }
    }

    auto prefetch = [&](int kt, int buf){
        size_t off = ((size_t)bh * Tq + (size_t)kt * 64) * Dh;
        const __half* k16 = g_k16 + off;
        const __half* v16 = g_v16 + off;
        #pragma unroll
        for (int v = 0; v < 2; v++){
            int idx = tid + v * 256;          // 0..511
            int row = idx >> 3;               // 0..63
            int c   = idx & 7;
            uint32_t sw = (uint32_t)(row * 128 + ((c ^ (row & 7)) << 4));
            cp16(sb + FS_K + buf*8192 + sw, k16 + (size_t)row * Dh + c * 8);
            cp16(sb + FS_V + buf*8192 + sw, v16 + (size_t)row * Dh + c * 8);
        }
        asm volatile("cp.async.commit_group;" ::: "memory");
    };

    prefetch(0, 0);

    float sO[8][4];
    #pragma unroll
    for (int i = 0; i < 8; i++)
        #pragma unroll
        for (int q = 0; q < 4; q++) sO[i][q] = 0.0f;
    float lac[4] = {0.f, 0.f, 0.f, 0.f};
    float m0 = -1e30f, m1 = -1e30f;

    const int rA = ((lane >> 3) & 1) * 8 + (lane & 7);
    const int cA = (lane >> 4) & 1;
    const int rB = lane & 15;
    const int cB = lane >> 4;
    const int qrow = w * 16 + rA;
    const uint32_t ONE2 = 0x3C003C00u;
    const uint32_t ob[2] = {ONE2, ONE2};

    for (int kt = 0; kt < nkb; kt++){
        int buf = kt & 1;
        if (kt + 1 < nkb){
            prefetch(kt + 1, buf ^ 1);
            asm volatile("cp.async.wait_group 1;" ::: "memory");
        } else {
            asm volatile("cp.async.wait_group 0;" ::: "memory");
        }
        __syncthreads();

        bool skip = (kt == 2*qt + 1) && (w < 4);
        if (!skip){
            // ---- S = Q @ K^T, single f16 pass ----
            float s[8][4];
            #pragma unroll
            for (int i = 0; i < 8; i++)
                #pragma unroll
                for (int q = 0; q < 4; q++) s[i][q] = 0.0f;

            uint32_t kb = sb + FS_K + buf*8192;
            #pragma unroll
            for (int ks = 0; ks < 4; ks++){
                uint32_t a[4];
                ldmx4(a, sb + FS_Q + qrow*128 + (((ks*2 + cA) ^ (qrow & 7)) << 4));
                #pragma unroll
                for (int j2 = 0; j2 < 4; j2++){
                    int krow = j2*16 + rB;
                    uint32_t br[4];
                    ldmx4(br, kb + krow*128 + (((ks*2 + cB) ^ (krow & 7)) << 4));
                    uint32_t b0[2] = {br[0], br[2]};
                    uint32_t b1[2] = {br[1], br[3]};
                    mma_f16(s[j2*2],     a, b0);
                    mma_f16(s[j2*2 + 1], a, b1);
                }
            }

            // ---- causal mask (diagonal region only) ----
            if (kt >= 2*qt){
                int co = (kt - 2*qt) * 64;
                int lr0 = w*16 + (lane >> 2);
                int lr1 = lr0 + 8;
                #pragma unroll
                for (int nt = 0; nt < 8; nt++){
                    int c0 = co + nt*8 + (lane & 3)*2;
                    if (c0     > lr0) s[nt][0] = -1e30f;
                    if (c0 + 1 > lr0) s[nt][1] = -1e30f;
                    if (c0     > lr1) s[nt][2] = -1e30f;
                    if (c0 + 1 > lr1) s[nt][3] = -1e30f;
                }
            }

            // ---- online softmax (base-2 domain) ----
            float mx0 = -1e30f, mx1 = -1e30f;
            #pragma unroll
            for (int nt = 0; nt < 8; nt++){
                mx0 = fmaxf(mx0, fmaxf(s[nt][0], s[nt][1]));
                mx1 = fmaxf(mx1, fmaxf(s[nt][2], s[nt][3]));
            }
            mx0 = fmaxf(mx0, __shfl_xor_sync(0xffffffffu, mx0, 1));
            mx0 = fmaxf(mx0, __shfl_xor_sync(0xffffffffu, mx0, 2));
            mx1 = fmaxf(mx1, __shfl_xor_sync(0xffffffffu, mx1, 1));
            mx1 = fmaxf(mx1, __shfl_xor_sync(0xffffffffu, mx1, 2));
            float mn0 = fmaxf(m0, mx0), mn1 = fmaxf(m1, mx1);
            float al0 = ex2f(m0 - mn0), al1 = ex2f(m1 - mn1);
            m0 = mn0; m1 = mn1;
            #pragma unroll
            for (int nt = 0; nt < 8; nt++){
                sO[nt][0] *= al0; sO[nt][1] *= al0;
                sO[nt][2] *= al1; sO[nt][3] *= al1;
            }
            lac[0] *= al0; lac[1] *= al0; lac[2] *= al1; lac[3] *= al1;

            // ---- P = 2^(s-m) in f16x2 (PV A-fragment layout) ----
            uint32_t P[8][2];
            #pragma unroll
            for (int nt = 0; nt < 8; nt++){
                P[nt][0] = ex2_f16x2(cvt_f16x2(s[nt][0] - mn0, s[nt][1] - mn0));
                P[nt][1] = ex2_f16x2(cvt_f16x2(s[nt][2] - mn1, s[nt][3] - mn1));
            }

            // ---- row sums: lac += P @ ones ----
            #pragma unroll
            for (int ks = 0; ks < 4; ks++){
                uint32_t a[4] = {P[2*ks][0], P[2*ks][1], P[2*ks+1][0], P[2*ks+1][1]};
                mma_f16(lac, a, ob);
            }

            // ---- O += P @ V, single f16 pass ----
            uint32_t vb = sb + FS_V + buf*8192;
            #pragma unroll
            for (int ks = 0; ks < 4; ks++){
                uint32_t a[4] = {P[2*ks][0], P[2*ks][1], P[2*ks+1][0], P[2*ks+1][1]};
                #pragma unroll
                for (int dt2 = 0; dt2 < 4; dt2++){
                    int vrow = ks*16 + (lane & 15);
                    int chnk = dt2*2 + (lane >> 4);
                    uint32_t br[4];
                    ldmx4t(br, vb + vrow*128 + ((chnk ^ (vrow & 7)) << 4));
                    uint32_t b0[2] = {br[0], br[1]};
                    uint32_t b1[2] = {br[2], br[3]};
                    mma_f16(sO[dt2*2],     a, b0);
                    mma_f16(sO[dt2*2 + 1], a, b1);
                }
            }
        }
        __syncthreads();
    }

    // ---- epilogue: normalize, write f16 at [b,t,h,d] ----
    float inv0 = 1.0f / lac[0];
    float inv1 = 1.0f / lac[2];
    int tr0 = qt*128 + w*16 + (lane >> 2);
    int tr1 = tr0 + 8;
    #pragma unroll
    for (int dt = 0; dt < 8; dt++){
        int d = dt*8 + (lane & 3)*2;
        size_t i0 = ((size_t)(b * Tq + tr0) * Hq + h) * Dh + d;
        size_t i1 = ((size_t)(b * Tq + tr1) * Hq + h) * Dh + d;
        *(__half2*)(g_o16 + i0) = __halves2half2(
            __float2half_rn(sO[dt][0] * inv0), __float2half_rn(sO[dt][1] * inv0));
        *(__half2*)(g_o16 + i1) = __halves2half2(
            __float2half_rn(sO[dt][2] * inv1), __float2half_rn(sO[dt][3] * inv1));
    }
}

// ---------------------------------------------------------------------------
extern "C" void kernel_launch(void* const* d_in, const int* in_sizes, int n_in,
                              void* d_out, int out_size)
{
    (void)in_sizes; (void)n_in; (void)out_size;
    const float* x     = (const float*)d_in[0];
    const float* cosT  = (const float*)d_in[1];
    const float* sinT  = (const float*)d_in[2];
    const float* w_qkv = (const float*)d_in[3];
    const float* w_out = (const float*)d_in[4];
    float* out = (float*)d_out;

    void *p_x16, *p_wq16, *p_wo16, *p_o16;
    cudaGetSymbolAddress(&p_x16,  g_x16);
    cudaGetSymbolAddress(&p_wq16, g_wq16);
    cudaGetSymbolAddress(&p_wo16, g_wo16);
    cudaGetSymbolAddress(&p_o16,  g_o16);

    cudaFuncSetAttribute(flash_tc, cudaFuncAttributeMaxDynamicSharedMemorySize, FLASH_SMEM);
    cudaFuncSetAttribute(h16_gemm<0>, cudaFuncAttributeMaxDynamicSharedMemorySize, GEMM_SMEM);
    cudaFuncSetAttribute(h16_gemm<1>, cudaFuncAttributeMaxDynamicSharedMemorySize, GEMM_SMEM);

    // 1) fp32 -> fp16 converts
    cvt16_kernel<<<(MROWS*Cq/4 + 255)/256, 256>>>(x, (__half*)p_x16, MROWS*Cq/4);
    cvt16_kernel<<<(3*Cq*Cq/4 + 255)/256, 256>>>(w_qkv, (__half*)p_wq16, 3*Cq*Cq/4);
    cvt16_kernel<<<(Cq*Cq/4 + 255)/256, 256>>>(w_out, (__half*)p_wo16, Cq*Cq/4);

    // 2) QKV projection: Q,K fp32; V f16
    {
        dim3 grid(3*Cq / 128, MROWS / 128);   // (24, 64)
        h16_gemm<1><<<grid, 256, GEMM_SMEM>>>((const __half*)p_x16, (const __half*)p_wq16,
                                              nullptr, Cq, 3*Cq);
    }
    // 3) RoPE -> f16 (Q scaled by log2e/8)
    rope_kernel<<<(Bq*Hq*Tq*32)/256, 256>>>(cosT, sinT);

    // 4) All-f16 tensor-core causal flash attention -> g_o16
    {
        dim3 grid(Tq / 128, Bq * Hq);
        flash_tc<<<grid, 256, FLASH_SMEM>>>();
    }

    // 5) Output projection
    {
        dim3 grid(Cq / 128, MROWS / 128);     // (8, 64)
        h16_gemm<0><<<grid, 256, GEMM_SMEM>>>((const __half*)p_o16, (const __half*)p_wo16,
                                              out, Cq, Cq);
    }
}

// round 8
// speedup vs baseline: 7.5534x; 1.0148x over previous
#include <cuda_runtime.h>
#include <cuda_bf16.h>
#include <cuda_fp16.h>
#include <cstdint>

#define Bq 4
#define Tq 2048
#define Cq 1024
#define Hq 16
#define Dh 64
#define MROWS (Bq*Tq)          // 8192
#define NHTD (Bq*Hq*Tq*Dh)     // 8,388,608

// ---------------------------------------------------------------------------
// Device-global scratch
// ---------------------------------------------------------------------------
__device__ __half g_q16[NHTD];           // post-rope, scaled log2e/8, f16 [b,h,t,d]
__device__ __half g_k16[NHTD];           // post-rope, f16 [b,h,t,d]
__device__ __half g_v16[NHTD];           // [b,h,t,d] f16

__device__ __half g_x16[MROWS*Cq];       // x in f16
__device__ __half g_wq16[3*Cq*Cq];       // w_qkv in f16
__device__ __half g_wo16[Cq*Cq];         // w_out in f16
__device__ __half g_o16[MROWS*Cq];       // attention output [b,t,h,d] f16

// ---------------------------------------------------------------------------
// helpers
// ---------------------------------------------------------------------------
__device__ __forceinline__ uint32_t s2u(const void* p){
    uint32_t a;
    asm("{ .reg .u64 t; cvta.to.shared.u64 t, %1; cvt.u32.u64 %0, t; }" : "=r"(a) : "l"(p));
    return a;
}
__device__ __forceinline__ void cp16(uint32_t dst, const void* src){
    asm volatile("cp.async.cg.shared.global [%0], [%1], 16;" :: "r"(dst), "l"(src));
}
__device__ __forceinline__ void ldmx4(uint32_t* r, uint32_t addr){
    asm volatile("ldmatrix.sync.aligned.m8n8.x4.shared.b16 {%0,%1,%2,%3}, [%4];"
                 : "=r"(r[0]), "=r"(r[1]), "=r"(r[2]), "=r"(r[3]) : "r"(addr));
}
__device__ __forceinline__ void ldmx4t(uint32_t* r, uint32_t addr){
    asm volatile("ldmatrix.sync.aligned.m8n8.x4.trans.shared.b16 {%0,%1,%2,%3}, [%4];"
                 : "=r"(r[0]), "=r"(r[1]), "=r"(r[2]), "=r"(r[3]) : "r"(addr));
}
__device__ __forceinline__ void mma_f16(float* c, const uint32_t* a, const uint32_t* b){
    asm volatile(
        "mma.sync.aligned.m16n8k16.row.col.f32.f16.f16.f32 "
        "{%0,%1,%2,%3}, {%4,%5,%6,%7}, {%8,%9}, {%0,%1,%2,%3};"
        : "+f"(c[0]), "+f"(c[1]), "+f"(c[2]), "+f"(c[3])
        : "r"(a[0]), "r"(a[1]), "r"(a[2]), "r"(a[3]), "r"(b[0]), "r"(b[1]));
}
__device__ __forceinline__ uint32_t cvt_f16x2(float lo, float hi){
    uint32_t r;
    asm("cvt.rn.f16x2.f32 %0, %1, %2;" : "=r"(r) : "f"(hi), "f"(lo));
    return r;
}
__device__ __forceinline__ uint32_t ex2_f16x2(uint32_t x){
    uint32_t r;
    asm("ex2.approx.f16x2 %0, %1;" : "=r"(r) : "r"(x));
    return r;
}
__device__ __forceinline__ float ex2f(float x){
    float r;
    asm("ex2.approx.ftz.f32 %0, %1;" : "=f"(r) : "f"(x));
    return r;
}

#define QSC 0.18033688011112042f   // log2(e)/8

// ---------------------------------------------------------------------------
// fp32 -> fp16 convert
// ---------------------------------------------------------------------------
__global__ void cvt16_kernel(const float* __restrict__ src,
                             __half* __restrict__ dst, int n4)
{
    int i = blockIdx.x * blockDim.x + threadIdx.x;
    if (i >= n4) return;
    float4 v = ((const float4*)src)[i];
    ((__half2*)dst)[2*i]   = __halves2half2(__float2half_rn(v.x), __float2half_rn(v.y));
    ((__half2*)dst)[2*i+1] = __halves2half2(__float2half_rn(v.z), __float2half_rn(v.w));
}

// ---------------------------------------------------------------------------
// Single-pass f16 HMMA GEMM, single-barrier multistage (3 stages).
// EPI=0: C[m,Nfull] fp32.
// EPI=1: QKV epilogue — V written f16 directly; Q/K staged through smem,
//        RoPE applied in-epilogue, written f16 to g_q16/g_k16 [b,h,t,d].
// ---------------------------------------------------------------------------
#define ROWB 128
#define OPB (128*ROWB)          // 16384 bytes per operand tile
#define STB (2*OPB)             // 32768 per stage (A+B)
#define GEMM_SMEM (3*STB)       // 98304
#define EPAD 132                // padded f32 row for epilogue staging

template<int EPI>
__global__ __launch_bounds__(256, 2)
void h16_gemm(const __half* __restrict__ A, const __half* __restrict__ B,
              float* __restrict__ C, int K, int Nfull,
              const float* __restrict__ cosT, const float* __restrict__ sinT)
{
    extern __shared__ __align__(16) char smem[];
    const uint32_t sb = s2u(smem);

    const int tid  = threadIdx.x;
    const int lane = tid & 31;
    const int wid  = tid >> 5;
    const int wM   = wid >> 2;
    const int wN   = wid & 3;
    const int bm = blockIdx.y * 128;
    const int bn = blockIdx.x * 128;
    const int NC = K >> 6;          // 64-wide k-chunks

    float acc[4][4][4];
    #pragma unroll
    for (int i = 0; i < 4; i++)
        #pragma unroll
        for (int j = 0; j < 4; j++)
            #pragma unroll
            for (int q = 0; q < 4; q++) acc[i][j][q] = 0.0f;

    const int rA = ((lane >> 3) & 1) * 8 + (lane & 7);
    const int cA = (lane >> 4) & 1;
    const int rB = lane & 15;
    const int cB = lane >> 4;

    auto prefetch = [&](int c, int st){
        uint32_t base = sb + st * STB;
        int kc = c << 6;
        #pragma unroll
        for (int v = 0; v < 4; v++){
            int idx = tid + v * 256;        // 0..1023
            int row = idx >> 3;             // 0..127
            int ch  = idx & 7;
            uint32_t sw = (uint32_t)(row * ROWB + ((ch ^ (row & 7)) << 4));
            cp16(base + sw,       A + (size_t)(bm + row) * K + kc + ch * 8);
            cp16(base + OPB + sw, B + (size_t)(bn + row) * K + kc + ch * 8);
        }
        asm volatile("cp.async.commit_group;" ::: "memory");
    };

    prefetch(0, 0);
    prefetch(1, 1);
    asm volatile("cp.async.wait_group 1;" ::: "memory");   // stage 0 ready
    __syncthreads();

    for (int c = 0; c < NC; c++){
        int st = c % 3;
        if (c + 2 < NC) prefetch(c + 2, (c + 2) % 3);      // overlaps compute(c)

        uint32_t ab = sb + st * STB;
        uint32_t bb = ab + OPB;
        #pragma unroll
        for (int ks = 0; ks < 4; ks++){
            uint32_t a[4][4];
            #pragma unroll
            for (int i = 0; i < 4; i++){
                int arow = wM*64 + i*16 + rA;
                ldmx4(a[i], ab + arow*ROWB + (((ks*2 + cA) ^ (arow & 7)) << 4));
            }
            uint32_t br[2][4];
            #pragma unroll
            for (int j2 = 0; j2 < 2; j2++){
                int brow = wN*32 + j2*16 + rB;
                ldmx4(br[j2], bb + brow*ROWB + (((ks*2 + cB) ^ (brow & 7)) << 4));
            }
            uint32_t b[4][2];
            #pragma unroll
            for (int j2 = 0; j2 < 2; j2++){
                b[j2*2+0][0] = br[j2][0]; b[j2*2+0][1] = br[j2][2];
                b[j2*2+1][0] = br[j2][1]; b[j2*2+1][1] = br[j2][3];
            }
            #pragma unroll
            for (int i = 0; i < 4; i++)
                #pragma unroll
                for (int j = 0; j < 4; j++)
                    mma_f16(acc[i][j], a[i], b[j]);
        }

        if (c + 1 < NC){
            if (c + 2 < NC){ asm volatile("cp.async.wait_group 1;" ::: "memory"); }
            else           { asm volatile("cp.async.wait_group 0;" ::: "memory"); }
            __syncthreads();
        }
    }

    const int g  = lane >> 2;
    const int tg = lane & 3;
    const int part = bn >> 10;

    if (EPI == 0 || part == 2){
        #pragma unroll
        for (int i = 0; i < 4; i++){
            #pragma unroll
            for (int j = 0; j < 4; j++){
                int col = bn + wN*32 + j*8 + tg*2;
                #pragma unroll
                for (int h2 = 0; h2 < 2; h2++){
                    int m = bm + wM*64 + i*16 + g + h2*8;
                    float2 val = make_float2(acc[i][j][h2*2], acc[i][j][h2*2+1]);
                    if (EPI == 0){
                        *(float2*)(C + (size_t)m * Nfull + col) = val;
                    } else {
                        int hh = (col >> 6) & (Hq - 1);
                        int d0 = col & (Dh - 1);
                        int b  = m >> 11;
                        int t  = m & (Tq - 1);
                        size_t idx = ((size_t)(b*Hq + hh) * Tq + t) * Dh + d0;
                        *(__half2*)(g_v16 + idx) = __halves2half2(
                            __float2half_rn(val.x), __float2half_rn(val.y));
                    }
                }
            }
        }
    } else {
        // Q or K tile: stage to smem, apply RoPE, write f16
        __syncthreads();                      // mainloop smem reads complete
        float* sf = (float*)smem;
        #pragma unroll
        for (int i = 0; i < 4; i++){
            #pragma unroll
            for (int j = 0; j < 4; j++){
                int cl = wN*32 + j*8 + tg*2;
                #pragma unroll
                for (int h2 = 0; h2 < 2; h2++){
                    int ml = wM*64 + i*16 + g + h2*8;
                    *(float2*)&sf[ml*EPAD + cl] =
                        make_float2(acc[i][j][h2*2], acc[i][j][h2*2+1]);
                }
            }
        }
        __syncthreads();

        for (int k = 0; k < 32; k++){
            int p    = tid + k * 256;         // 0..8191
            int row  = p >> 6;                // 0..127
            int pd   = p & 63;
            int hloc = pd >> 5;               // head within tile (0/1)
            int d    = pd & 31;
            int m    = bm + row;
            int t    = m & (Tq - 1);
            int b    = m >> 11;
            float cv = cosT[t * Dh + d];      // cos[t][d] == cos[t][d+32]
            float sv = sinT[t * Dh + d];
            float u1 = sf[row * EPAD + hloc*64 + d];
            float u2 = sf[row * EPAD + hloc*64 + 32 + d];
            float r1 = u1 * cv - u2 * sv;
            float r2 = u2 * cv + u1 * sv;
            int colg = bn + hloc * 64;
            int h    = (colg >> 6) & (Hq - 1);
            size_t idx = ((size_t)(b*Hq + h) * Tq + t) * Dh + d;
            if (part == 0){
                g_q16[idx]      = __float2half_rn(r1 * QSC);
                g_q16[idx + 32] = __float2half_rn(r2 * QSC);
            } else {
                g_k16[idx]      = __float2half_rn(r1);
                g_k16[idx + 32] = __float2half_rn(r2);
            }
        }
    }
}

// ---------------------------------------------------------------------------
// Tensor-core flash attention (causal), all-f16 single-pass,
// single-barrier double-buffered mainloop.
// ---------------------------------------------------------------------------
#define FS_Q 0            // 128 x 128B
#define FS_K 16384        // buf b: +b*8192
#define FS_V 32768        // buf b: +b*8192
#define FLASH_SMEM 49152

__global__ __launch_bounds__(256)
void flash_tc()
{
    extern __shared__ __align__(1024) char fsm[];
    const uint32_t sb = s2u(fsm);
    const int tid  = threadIdx.x;
    const int lane = tid & 31;
    const int w    = tid >> 5;
    const int qt   = (int)(gridDim.x - 1 - blockIdx.x);
    const int bh   = blockIdx.y;
    const int b    = bh >> 4, h = bh & (Hq - 1);
    const int nkb  = 2 * qt + 2;

    // ---- load Q tile (f16), swizzled 128B rows ----
    {
        const __half* q16 = g_q16 + ((size_t)bh * Tq + (size_t)qt * 128) * Dh;
        #pragma unroll
        for (int v = 0; v < 4; v++){
            int idx = tid + v * 256;          // 0..1023
            int row = idx >> 3;               // 0..127
            int c   = idx & 7;
            uint32_t sw = (uint32_t)(row * 128 + ((c ^ (row & 7)) << 4));
            cp16(sb + FS_Q + sw, q16 + (size_t)row * Dh + c * 8);
        }
    }

    auto prefetch = [&](int kt, int buf){
        size_t off = ((size_t)bh * Tq + (size_t)kt * 64) * Dh;
        const __half* k16 = g_k16 + off;
        const __half* v16 = g_v16 + off;
        #pragma unroll
        for (int v = 0; v < 2; v++){
            int idx = tid + v * 256;          // 0..511
            int row = idx >> 3;               // 0..63
            int c   = idx & 7;
            uint32_t sw = (uint32_t)(row * 128 + ((c ^ (row & 7)) << 4));
            cp16(sb + FS_K + buf*8192 + sw, k16 + (size_t)row * Dh + c * 8);
            cp16(sb + FS_V + buf*8192 + sw, v16 + (size_t)row * Dh + c * 8);
        }
        asm volatile("cp.async.commit_group;" ::: "memory");
    };

    prefetch(0, 0);   // includes Q loads in the same group
    asm volatile("cp.async.wait_group 0;" ::: "memory");
    __syncthreads();

    float sO[8][4];
    #pragma unroll
    for (int i = 0; i < 8; i++)
        #pragma unroll
        for (int q = 0; q < 4; q++) sO[i][q] = 0.0f;
    float lac[4] = {0.f, 0.f, 0.f, 0.f};
    float m0 = -1e30f, m1 = -1e30f;

    const int rA = ((lane >> 3) & 1) * 8 + (lane & 7);
    const int cA = (lane >> 4) & 1;
    const int rB = lane & 15;
    const int cB = lane >> 4;
    const int qrow = w * 16 + rA;
    const uint32_t ONE2 = 0x3C003C00u;
    const uint32_t ob[2] = {ONE2, ONE2};

    for (int kt = 0; kt < nkb; kt++){
        int buf = kt & 1;
        if (kt + 1 < nkb) prefetch(kt + 1, buf ^ 1);   // overlaps compute(kt)

        bool skip = (kt == 2*qt + 1) && (w < 4);
        if (!skip){
            // ---- S = Q @ K^T, single f16 pass ----
            float s[8][4];
            #pragma unroll
            for (int i = 0; i < 8; i++)
                #pragma unroll
                for (int q = 0; q < 4; q++) s[i][q] = 0.0f;

            uint32_t kb = sb + FS_K + buf*8192;
            #pragma unroll
            for (int ks = 0; ks < 4; ks++){
                uint32_t a[4];
                ldmx4(a, sb + FS_Q + qrow*128 + (((ks*2 + cA) ^ (qrow & 7)) << 4));
                #pragma unroll
                for (int j2 = 0; j2 < 4; j2++){
                    int krow = j2*16 + rB;
                    uint32_t br[4];
                    ldmx4(br, kb + krow*128 + (((ks*2 + cB) ^ (krow & 7)) << 4));
                    uint32_t b0[2] = {br[0], br[2]};
                    uint32_t b1[2] = {br[1], br[3]};
                    mma_f16(s[j2*2],     a, b0);
                    mma_f16(s[j2*2 + 1], a, b1);
                }
            }

            // ---- causal mask (diagonal region only) ----
            if (kt >= 2*qt){
                int co = (kt - 2*qt) * 64;
                int lr0 = w*16 + (lane >> 2);
                int lr1 = lr0 + 8;
                #pragma unroll
                for (int nt = 0; nt < 8; nt++){
                    int c0 = co + nt*8 + (lane & 3)*2;
                    if (c0     > lr0) s[nt][0] = -1e30f;
                    if (c0 + 1 > lr0) s[nt][1] = -1e30f;
                    if (c0     > lr1) s[nt][2] = -1e30f;
                    if (c0 + 1 > lr1) s[nt][3] = -1e30f;
                }
            }

            // ---- online softmax (base-2 domain) ----
            float mx0 = -1e30f, mx1 = -1e30f;
            #pragma unroll
            for (int nt = 0; nt < 8; nt++){
                mx0 = fmaxf(mx0, fmaxf(s[nt][0], s[nt][1]));
                mx1 = fmaxf(mx1, fmaxf(s[nt][2], s[nt][3]));
            }
            mx0 = fmaxf(mx0, __shfl_xor_sync(0xffffffffu, mx0, 1));
            mx0 = fmaxf(mx0, __shfl_xor_sync(0xffffffffu, mx0, 2));
            mx1 = fmaxf(mx1, __shfl_xor_sync(0xffffffffu, mx1, 1));
            mx1 = fmaxf(mx1, __shfl_xor_sync(0xffffffffu, mx1, 2));
            float mn0 = fmaxf(m0, mx0), mn1 = fmaxf(m1, mx1);
            float al0 = ex2f(m0 - mn0), al1 = ex2f(m1 - mn1);
            m0 = mn0; m1 = mn1;
            #pragma unroll
            for (int nt = 0; nt < 8; nt++){
                sO[nt][0] *= al0; sO[nt][1] *= al0;
                sO[nt][2] *= al1; sO[nt][3] *= al1;
            }
            lac[0] *= al0; lac[1] *= al0; lac[2] *= al1; lac[3] *= al1;

            // ---- P = 2^(s-m) in f16x2 (PV A-fragment layout) ----
            uint32_t P[8][2];
            #pragma unroll
            for (int nt = 0; nt < 8; nt++){
                P[nt][0] = ex2_f16x2(cvt_f16x2(s[nt][0] - mn0, s[nt][1] - mn0));
                P[nt][1] = ex2_f16x2(cvt_f16x2(s[nt][2] - mn1, s[nt][3] - mn1));
            }

            // ---- row sums: lac += P @ ones ----
            #pragma unroll
            for (int ks = 0; ks < 4; ks++){
                uint32_t a[4] = {P[2*ks][0], P[2*ks][1], P[2*ks+1][0], P[2*ks+1][1]};
                mma_f16(lac, a, ob);
            }

            // ---- O += P @ V, single f16 pass ----
            uint32_t vb = sb + FS_V + buf*8192;
            #pragma unroll
            for (int ks = 0; ks < 4; ks++){
                uint32_t a[4] = {P[2*ks][0], P[2*ks][1], P[2*ks+1][0], P[2*ks+1][1]};
                #pragma unroll
                for (int dt2 = 0; dt2 < 4; dt2++){
                    int vrow = ks*16 + (lane & 15);
                    int chnk = dt2*2 + (lane >> 4);
                    uint32_t br[4];
                    ldmx4t(br, vb + vrow*128 + ((chnk ^ (vrow & 7)) << 4));
                    uint32_t b0[2] = {br[0], br[1]};
                    uint32_t b1[2] = {br[2], br[3]};
                    mma_f16(sO[dt2*2],     a, b0);
                    mma_f16(sO[dt2*2 + 1], a, b1);
                }
            }
        }

        if (kt + 1 < nkb){
            asm volatile("cp.async.wait_group 0;" ::: "memory");
            __syncthreads();
        }
    }

    // ---- epilogue: normalize, write f16 at [b,t,h,d] ----
    float inv0 = 1.0f / lac[0];
    float inv1 = 1.0f / lac[2];
    int tr0 = qt*128 + w*16 + (lane >> 2);
    int tr1 = tr0 + 8;
    #pragma unroll
    for (int dt = 0; dt < 8; dt++){
        int d = dt*8 + (lane & 3)*2;
        size_t i0 = ((size_t)(b * Tq + tr0) * Hq + h) * Dh + d;
        size_t i1 = ((size_t)(b * Tq + tr1) * Hq + h) * Dh + d;
        *(__half2*)(g_o16 + i0) = __halves2half2(
            __float2half_rn(sO[dt][0] * inv0), __float2half_rn(sO[dt][1] * inv0));
        *(__half2*)(g_o16 + i1) = __halves2half2(
            __float2half_rn(sO[dt][2] * inv1), __float2half_rn(sO[dt][3] * inv1));
    }
}

// ---------------------------------------------------------------------------
extern "C" void kernel_launch(void* const* d_in, const int* in_sizes, int n_in,
                              void* d_out, int out_size)
{
    (void)in_sizes; (void)n_in; (void)out_size;
    const float* x     = (const float*)d_in[0];
    const float* cosT  = (const float*)d_in[1];
    const float* sinT  = (const float*)d_in[2];
    const float* w_qkv = (const float*)d_in[3];
    const float* w_out = (const float*)d_in[4];
    float* out = (float*)d_out;

    void *p_x16, *p_wq16, *p_wo16, *p_o16;
    cudaGetSymbolAddress(&p_x16,  g_x16);
    cudaGetSymbolAddress(&p_wq16, g_wq16);
    cudaGetSymbolAddress(&p_wo16, g_wo16);
    cudaGetSymbolAddress(&p_o16,  g_o16);

    cudaFuncSetAttribute(flash_tc, cudaFuncAttributeMaxDynamicSharedMemorySize, FLASH_SMEM);
    cudaFuncSetAttribute(h16_gemm<0>, cudaFuncAttributeMaxDynamicSharedMemorySize, GEMM_SMEM);
    cudaFuncSetAttribute(h16_gemm<1>, cudaFuncAttributeMaxDynamicSharedMemorySize, GEMM_SMEM);

    // 1) fp32 -> fp16 converts
    cvt16_kernel<<<(MROWS*Cq/4 + 255)/256, 256>>>(x, (__half*)p_x16, MROWS*Cq/4);
    cvt16_kernel<<<(3*Cq*Cq/4 + 255)/256, 256>>>(w_qkv, (__half*)p_wq16, 3*Cq*Cq/4);
    cvt16_kernel<<<(Cq*Cq/4 + 255)/256, 256>>>(w_out, (__half*)p_wo16, Cq*Cq/4);

    // 2) QKV projection with fused RoPE epilogue: Q,K f16 (rotated), V f16
    {
        dim3 grid(3*Cq / 128, MROWS / 128);   // (24, 64)
        h16_gemm<1><<<grid, 256, GEMM_SMEM>>>((const __half*)p_x16, (const __half*)p_wq16,
                                              nullptr, Cq, 3*Cq, cosT, sinT);
    }

    // 3) All-f16 tensor-core causal flash attention -> g_o16
    {
        dim3 grid(Tq / 128, Bq * Hq);
        flash_tc<<<grid, 256, FLASH_SMEM>>>();
    }

    // 4) Output projection
    {
        dim3 grid(Cq / 128, MROWS / 128);     // (8, 64)
        h16_gemm<0><<<grid, 256, GEMM_SMEM>>>((const __half*)p_o16, (const __half*)p_wo16,
                                              out, Cq, Cq, nullptr, nullptr);
    }
}